// round 8
// baseline (speedup 1.0000x reference)
#include <cuda_runtime.h>
#include <cuda_bf16.h>
#include <math.h>
#include <cstdint>

#define S_LEN   1024
#define B_N     4
#define D_MODEL 4096
#define HQ_N    32
#define HKV_N   8
#define HD_N    128
#define MROWS   4096
#define KDIM    4096
#define ATTN_SCALE 0.08838834764831845f

typedef unsigned long long u64;

__device__ __forceinline__ uint32_t smem_u32(const void* p) {
    uint32_t a;
    asm("{ .reg .u64 t; cvta.to.shared.u64 t, %1; cvt.u32.u64 %0, t; }" : "=r"(a) : "l"(p));
    return a;
}
__device__ __forceinline__ void mma_bf16(float (&d)[4], const uint32_t (&a)[4],
                                         const uint32_t b0, const uint32_t b1) {
    asm volatile(
        "mma.sync.aligned.m16n8k16.row.col.f32.bf16.bf16.f32 "
        "{%0,%1,%2,%3}, {%4,%5,%6,%7}, {%8,%9}, {%0,%1,%2,%3};"
        : "+f"(d[0]), "+f"(d[1]), "+f"(d[2]), "+f"(d[3])
        : "r"(a[0]), "r"(a[1]), "r"(a[2]), "r"(a[3]), "r"(b0), "r"(b1));
}
__device__ __forceinline__ void ldm_x4(uint32_t (&r)[4], uint32_t addr) {
    asm volatile("ldmatrix.sync.aligned.m8n8.x4.shared.b16 {%0,%1,%2,%3}, [%4];"
                 : "=r"(r[0]), "=r"(r[1]), "=r"(r[2]), "=r"(r[3]) : "r"(addr));
}
__device__ __forceinline__ void ldm_x4_t(uint32_t (&r)[4], uint32_t addr) {
    asm volatile("ldmatrix.sync.aligned.m8n8.x4.trans.shared.b16 {%0,%1,%2,%3}, [%4];"
                 : "=r"(r[0]), "=r"(r[1]), "=r"(r[2]), "=r"(r[3]) : "r"(addr));
}
__device__ __forceinline__ void split1(float x, __nv_bfloat16& h, __nv_bfloat16& l) {
    h = __float2bfloat16_rn(x);
    l = __float2bfloat16_rn(x - __bfloat162float(h));
}
__device__ __forceinline__ void cp16(uint32_t dst, const void* src) {
    asm volatile("cp.async.cg.shared.global [%0], [%1], 16;" :: "r"(dst), "l"(src));
}
#define CP_COMMIT() asm volatile("cp.async.commit_group;" ::: "memory")
#define CP_WAIT1()  asm volatile("cp.async.wait_group 1;" ::: "memory")

// ---------------------------------------------------------------------------
// Scratch
// ---------------------------------------------------------------------------
__device__ float g_Q[(size_t)MROWS * (HQ_N * HD_N)];
__device__ float g_K[(size_t)MROWS * (HKV_N * HD_N)];
__device__ float g_V[(size_t)MROWS * (HKV_N * HD_N)];

__device__ __nv_bfloat16 g_h_hi[(size_t)MROWS * D_MODEL];
__device__ __nv_bfloat16 g_h_lo[(size_t)MROWS * D_MODEL];
__device__ __nv_bfloat16 g_wq_hi[(size_t)4096 * 4096];
__device__ __nv_bfloat16 g_wq_lo[(size_t)4096 * 4096];
__device__ __nv_bfloat16 g_wk_hi[(size_t)1024 * 4096];
__device__ __nv_bfloat16 g_wk_lo[(size_t)1024 * 4096];
__device__ __nv_bfloat16 g_wv_hi[(size_t)1024 * 4096];
__device__ __nv_bfloat16 g_wv_lo[(size_t)1024 * 4096];
__device__ __nv_bfloat16 g_wo_hi[(size_t)4096 * 4096];
__device__ __nv_bfloat16 g_wo_lo[(size_t)4096 * 4096];
__device__ __nv_bfloat16 g_a_hi[(size_t)MROWS * D_MODEL];
__device__ __nv_bfloat16 g_a_lo[(size_t)MROWS * D_MODEL];
__device__ __nv_bfloat16 g_kh[(size_t)MROWS * (HKV_N * HD_N)];
__device__ __nv_bfloat16 g_kl[(size_t)MROWS * (HKV_N * HD_N)];
__device__ __nv_bfloat16 g_vh[(size_t)MROWS * (HKV_N * HD_N)];
__device__ __nv_bfloat16 g_vl[(size_t)MROWS * (HKV_N * HD_N)];

// ---------------------------------------------------------------------------
// fp32 -> bf16 split
// ---------------------------------------------------------------------------
__global__ void split_bf16(const float* __restrict__ X,
                           __nv_bfloat16* __restrict__ H,
                           __nv_bfloat16* __restrict__ L, int n4) {
    int i = blockIdx.x * blockDim.x + threadIdx.x;
    if (i >= n4) return;
    float4 x = *(const float4*)(X + (size_t)i * 4);
    __nv_bfloat16 h0, h1, h2, h3, l0, l1, l2, l3;
    split1(x.x, h0, l0); split1(x.y, h1, l1);
    split1(x.z, h2, l2); split1(x.w, h3, l3);
    __nv_bfloat162* Hp = (__nv_bfloat162*)(H + (size_t)i * 4);
    __nv_bfloat162* Lp = (__nv_bfloat162*)(L + (size_t)i * 4);
    Hp[0] = __nv_bfloat162(h0, h1); Hp[1] = __nv_bfloat162(h2, h3);
    Lp[0] = __nv_bfloat162(l0, l1); Lp[1] = __nv_bfloat162(l2, l3);
}

// ---------------------------------------------------------------------------
// K/V prep: RoPE+split K, split V
// ---------------------------------------------------------------------------
__global__ void kv_prep(const float* __restrict__ K, const float* __restrict__ V,
                        const float* __restrict__ cosb, const float* __restrict__ sinb,
                        __nv_bfloat16* __restrict__ Kh, __nv_bfloat16* __restrict__ Kl,
                        __nv_bfloat16* __restrict__ Vh, __nv_bfloat16* __restrict__ Vl) {
    int idx = blockIdx.x * blockDim.x + threadIdx.x;
    if (idx >= MROWS * HKV_N * 64) return;
    int d = idx & 63;
    int h = (idx >> 6) & 7;
    int bs = idx >> 9;
    int s = bs & (S_LEN - 1);
    float c  = cosb[s * HD_N + 64 + d];
    float sn = sinb[s * HD_N + 64 + d];
    size_t base = (size_t)bs * (HKV_N * HD_N) + h * HD_N + d;
    float x1 = K[base], x2 = K[base + 64];
    float r1 = x1 * c - x2 * sn;
    float r2 = x2 * c + x1 * sn;
    split1(r1, Kh[base], Kl[base]);
    split1(r2, Kh[base + 64], Kl[base + 64]);
    split1(V[base], Vh[base], Vl[base]);
    split1(V[base + 64], Vh[base + 64], Vl[base + 64]);
}

// ---------------------------------------------------------------------------
// bf16-split GEMM via mma.sync + cp.async 3-stage pipeline (single change
// vs R7: replaces register-staged double buffer)
// ---------------------------------------------------------------------------
#define SROW   80
#define ATILE  (128 * SROW)
#define STAGE  (4 * ATILE)          // 40960
#define SM_GEMM (3 * STAGE)         // 122880
#define NCHUNK (KDIM / 32)

__global__ void __launch_bounds__(256, 1) gemm_bf16s(
    const __nv_bfloat16* __restrict__ A1, const __nv_bfloat16* __restrict__ A2,
    const __nv_bfloat16* __restrict__ B1, const __nv_bfloat16* __restrict__ B2,
    float* __restrict__ C, int Nn) {
    extern __shared__ char smem[];
    const uint32_t smb = smem_u32(smem);
    const int tid = threadIdx.x;
    const int wid = tid >> 5;
    const int lane = tid & 31;
    const int wm = (wid >> 2) << 6;
    const int wn = (wid & 3) << 5;
    const int n0 = blockIdx.x << 7;
    const int m0 = blockIdx.y << 7;

    const __nv_bfloat16* srcs[4] = {
        A1 + (size_t)m0 * KDIM, A2 + (size_t)m0 * KDIM,
        B1 + (size_t)n0 * KDIM, B2 + (size_t)n0 * KDIM };

    const int r_ld[2] = { tid >> 2, (tid + 256) >> 2 };
    const int s_off = (tid & 3) << 3;   // halves

    float acc[4][4][4];
#pragma unroll
    for (int i = 0; i < 4; i++)
#pragma unroll
        for (int j = 0; j < 4; j++)
#pragma unroll
            for (int t = 0; t < 4; t++) acc[i][j][t] = 0.f;

    // prologue: chunks 0,1 -> stages 0,1
#pragma unroll
    for (int pc = 0; pc < 2; pc++) {
        const int k0 = pc << 5;
#pragma unroll
        for (int arr = 0; arr < 4; arr++)
#pragma unroll
            for (int i = 0; i < 2; i++)
                cp16(smb + pc * STAGE + arr * ATILE + r_ld[i] * SROW + (s_off << 1),
                     srcs[arr] + (size_t)r_ld[i] * KDIM + k0 + s_off);
        CP_COMMIT();
    }

    const uint32_t a_lrow = (lane & 15);
    const uint32_t a_lkh  = (lane >> 4) << 4;
    const uint32_t b_lrow = (lane & 7) + ((lane >> 4) << 3);
    const uint32_t b_lkh  = ((lane >> 3) & 1) << 4;

    int stage = 0;
    for (int c = 0; c < NCHUNK; c++) {
        CP_WAIT1();
        __syncthreads();

        if (c + 2 < NCHUNK) {
            const int k0 = (c + 2) << 5;
            int st2 = stage + 2; if (st2 >= 3) st2 -= 3;
#pragma unroll
            for (int arr = 0; arr < 4; arr++)
#pragma unroll
                for (int i = 0; i < 2; i++)
                    cp16(smb + st2 * STAGE + arr * ATILE + r_ld[i] * SROW + (s_off << 1),
                         srcs[arr] + (size_t)r_ld[i] * KDIM + k0 + s_off);
        }
        CP_COMMIT();

        const uint32_t sb = smb + stage * STAGE;
#pragma unroll
        for (int ks = 0; ks < 2; ks++) {
            const uint32_t ko = ks << 5;
            uint32_t a1[4][4], a2[4][4];
#pragma unroll
            for (int i = 0; i < 4; i++) {
                uint32_t rowb = (wm + (i << 4) + a_lrow) * SROW + ko + a_lkh;
                ldm_x4(a1[i], sb + 0 * ATILE + rowb);
                ldm_x4(a2[i], sb + 1 * ATILE + rowb);
            }
            uint32_t b1[2][4], b2[2][4];
#pragma unroll
            for (int j2 = 0; j2 < 2; j2++) {
                uint32_t rowb = (wn + (j2 << 4) + b_lrow) * SROW + ko + b_lkh;
                ldm_x4(b1[j2], sb + 2 * ATILE + rowb);
                ldm_x4(b2[j2], sb + 3 * ATILE + rowb);
            }
#pragma unroll
            for (int i = 0; i < 4; i++)
#pragma unroll
                for (int j = 0; j < 4; j++) {
                    const uint32_t* bb1 = &b1[j >> 1][(j & 1) << 1];
                    const uint32_t* bb2 = &b2[j >> 1][(j & 1) << 1];
                    mma_bf16(acc[i][j], a1[i], bb1[0], bb1[1]);
                    mma_bf16(acc[i][j], a1[i], bb2[0], bb2[1]);
                    mma_bf16(acc[i][j], a2[i], bb1[0], bb1[1]);
                }
        }
        if (++stage == 3) stage = 0;
    }

    const int erow = m0 + wm + (lane >> 2);
    const int ecol = n0 + wn + ((lane & 3) << 1);
#pragma unroll
    for (int i = 0; i < 4; i++) {
#pragma unroll
        for (int j = 0; j < 4; j++) {
            float* p0 = C + (size_t)(erow + (i << 4)) * Nn + ecol + (j << 3);
            float* p1 = p0 + (size_t)8 * Nn;
            *(float2*)p0 = make_float2(acc[i][j][0], acc[i][j][1]);
            *(float2*)p1 = make_float2(acc[i][j][2], acc[i][j][3]);
        }
    }
}

// ---------------------------------------------------------------------------
// Tensor-core attention (exact R7 version)
// ---------------------------------------------------------------------------
#define QKV_RS 136
#define P_RS   72
#define SM_QH  0
#define SM_QL  17408
#define SM_KH  34816
#define SM_KL  52224
#define SM_VH  69632
#define SM_VL  87040
#define SM_PH  104448
#define SM_PL  113664
#define SM_RS  122880
#define SM_ATTN (SM_RS + 512)

__global__ void __launch_bounds__(256, 1) attn_tc(
    const float* __restrict__ Q,
    const __nv_bfloat16* __restrict__ Kh, const __nv_bfloat16* __restrict__ Kl,
    const __nv_bfloat16* __restrict__ Vh, const __nv_bfloat16* __restrict__ Vl,
    const float* __restrict__ cosb, const float* __restrict__ sinb,
    __nv_bfloat16* __restrict__ Oh, __nv_bfloat16* __restrict__ Ol) {
    extern __shared__ char smem[];
    const uint32_t smb = smem_u32(smem);
    const int tid = threadIdx.x;
    const int wid = tid >> 5;
    const int lane = tid & 31;
    const int b   = blockIdx.x >> 5;
    const int h   = blockIdx.x & 31;
    const int kvh = h >> 2;
    const int q0  = blockIdx.y << 6;

    const uint32_t a_lrow = (lane & 15);
    const uint32_t a_lkh  = (lane >> 4) << 4;
    const uint32_t b_lrow = (lane & 7) + ((lane >> 4) << 3);
    const uint32_t b_lkh  = ((lane >> 3) & 1) << 4;
    const int wq = (wid & 3) << 4;
    const int wk = (wid >> 2) << 5;

#pragma unroll
    for (int it = 0; it < 4; it++) {
        int slot = tid + (it << 8);
        int r = slot >> 4;
        int d = (slot & 15) << 2;
        int srow = q0 + r;
        const float* src = Q + ((size_t)(b * S_LEN + srow)) * (HQ_N * HD_N) + h * HD_N + d;
        float4 x1 = *(const float4*)(src);
        float4 x2 = *(const float4*)(src + 64);
        float4 cs = *(const float4*)(cosb + srow * HD_N + 64 + d);
        float4 sn = *(const float4*)(sinb + srow * HD_N + 64 + d);
        float o1[4] = { (x1.x * cs.x - x2.x * sn.x) * ATTN_SCALE,
                        (x1.y * cs.y - x2.y * sn.y) * ATTN_SCALE,
                        (x1.z * cs.z - x2.z * sn.z) * ATTN_SCALE,
                        (x1.w * cs.w - x2.w * sn.w) * ATTN_SCALE };
        float o2[4] = { (x2.x * cs.x + x1.x * sn.x) * ATTN_SCALE,
                        (x2.y * cs.y + x1.y * sn.y) * ATTN_SCALE,
                        (x2.z * cs.z + x1.z * sn.z) * ATTN_SCALE,
                        (x2.w * cs.w + x1.w * sn.w) * ATTN_SCALE };
        __nv_bfloat16* qh = (__nv_bfloat16*)(smem + SM_QH) + r * QKV_RS;
        __nv_bfloat16* ql = (__nv_bfloat16*)(smem + SM_QL) + r * QKV_RS;
#pragma unroll
        for (int u = 0; u < 4; u++) {
            split1(o1[u], qh[d + u], ql[d + u]);
            split1(o2[u], qh[d + 64 + u], ql[d + 64 + u]);
        }
    }

    float oacc[4][2][4];
#pragma unroll
    for (int i = 0; i < 4; i++)
#pragma unroll
        for (int j = 0; j < 2; j++)
#pragma unroll
            for (int t = 0; t < 4; t++) oacc[i][j][t] = 0.f;
    float rs0 = 0.f, rs1 = 0.f;

    const __nv_bfloat16* kvsrc[4] = { Kh, Kl, Vh, Vl };
    const uint32_t kvdst[4] = { SM_KH, SM_KL, SM_VH, SM_VL };

    for (int kt = 0; kt < S_LEN; kt += 64) {
        __syncthreads();

#pragma unroll
        for (int arr = 0; arr < 4; arr++) {
            const __nv_bfloat16* src = kvsrc[arr]
                + ((size_t)(b * S_LEN + kt)) * (HKV_N * HD_N) + kvh * HD_N;
            char* dst = smem + kvdst[arr];
#pragma unroll
            for (int it = 0; it < 4; it++) {
                int slot = tid + (it << 8);
                int r = slot >> 4;
                int cs = slot & 15;
                *(uint4*)(dst + r * (QKV_RS * 2) + (cs << 4)) =
                    *(const uint4*)(src + (size_t)r * (HKV_N * HD_N) + (cs << 3));
            }
        }
        __syncthreads();

        float sacc[4][4];
#pragma unroll
        for (int i = 0; i < 4; i++)
#pragma unroll
            for (int t = 0; t < 4; t++) sacc[i][t] = 0.f;

#pragma unroll
        for (int ks = 0; ks < 8; ks++) {
            const uint32_t ko = ks << 5;
            uint32_t ah[4], al[4];
            {
                uint32_t rowb = (wq + a_lrow) * (QKV_RS * 2) + ko + a_lkh;
                ldm_x4(ah, smb + SM_QH + rowb);
                ldm_x4(al, smb + SM_QL + rowb);
            }
            uint32_t bh[2][4], bl[2][4];
#pragma unroll
            for (int g = 0; g < 2; g++) {
                uint32_t rowb = (wk + (g << 4) + b_lrow) * (QKV_RS * 2) + ko + b_lkh;
                ldm_x4(bh[g], smb + SM_KH + rowb);
                ldm_x4(bl[g], smb + SM_KL + rowb);
            }
#pragma unroll
            for (int g = 0; g < 2; g++)
#pragma unroll
                for (int sub = 0; sub < 2; sub++) {
                    int nidx = (g << 1) + sub;
                    const uint32_t* h2 = &bh[g][sub << 1];
                    const uint32_t* l2 = &bl[g][sub << 1];
                    mma_bf16(sacc[nidx], ah, h2[0], h2[1]);
                    mma_bf16(sacc[nidx], ah, l2[0], l2[1]);
                    mma_bf16(sacc[nidx], al, h2[0], h2[1]);
                }
        }

        float ps0 = 0.f, ps1 = 0.f;
        const int prow0 = wq + (lane >> 2);
#pragma unroll
        for (int f = 0; f < 4; f++) {
            float p0 = __expf(sacc[f][0]);
            float p1 = __expf(sacc[f][1]);
            float p2 = __expf(sacc[f][2]);
            float p3 = __expf(sacc[f][3]);
            ps0 += p0 + p1;
            ps1 += p2 + p3;
            int col = wk + (f << 3) + ((lane & 3) << 1);
            __nv_bfloat16 h0, l0, h1, l1;
            split1(p0, h0, l0); split1(p1, h1, l1);
            *(__nv_bfloat162*)((__nv_bfloat16*)(smem + SM_PH) + prow0 * P_RS + col) = __nv_bfloat162(h0, h1);
            *(__nv_bfloat162*)((__nv_bfloat16*)(smem + SM_PL) + prow0 * P_RS + col) = __nv_bfloat162(l0, l1);
            split1(p2, h0, l0); split1(p3, h1, l1);
            *(__nv_bfloat162*)((__nv_bfloat16*)(smem + SM_PH) + (prow0 + 8) * P_RS + col) = __nv_bfloat162(h0, h1);
            *(__nv_bfloat162*)((__nv_bfloat16*)(smem + SM_PL) + (prow0 + 8) * P_RS + col) = __nv_bfloat162(l0, l1);
        }
        ps0 += __shfl_xor_sync(0xFFFFFFFF, ps0, 1);
        ps0 += __shfl_xor_sync(0xFFFFFFFF, ps0, 2);
        ps1 += __shfl_xor_sync(0xFFFFFFFF, ps1, 1);
        ps1 += __shfl_xor_sync(0xFFFFFFFF, ps1, 2);
        rs0 += ps0;
        rs1 += ps1;
        __syncthreads();

        const int nb = wid << 4;
#pragma unroll
        for (int ks = 0; ks < 4; ks++) {
            uint32_t vbh[4], vbl[4];
            {
                uint32_t rowb = ((ks << 4) + (lane & 15)) * (QKV_RS * 2) + ((nb + ((lane >> 4) << 3)) << 1);
                ldm_x4_t(vbh, smb + SM_VH + rowb);
                ldm_x4_t(vbl, smb + SM_VL + rowb);
            }
#pragma unroll
            for (int mt = 0; mt < 4; mt++) {
                uint32_t pah[4], pal[4];
                uint32_t rowb = ((mt << 4) + a_lrow) * (P_RS * 2) + (ks << 5) + a_lkh;
                ldm_x4(pah, smb + SM_PH + rowb);
                ldm_x4(pal, smb + SM_PL + rowb);
#pragma unroll
                for (int sub = 0; sub < 2; sub++) {
                    const uint32_t* h2 = &vbh[sub << 1];
                    const uint32_t* l2 = &vbl[sub << 1];
                    mma_bf16(oacc[mt][sub], pah, h2[0], h2[1]);
                    mma_bf16(oacc[mt][sub], pah, l2[0], l2[1]);
                    mma_bf16(oacc[mt][sub], pal, h2[0], h2[1]);
                }
            }
        }
    }

    float* rssm = (float*)(smem + SM_RS);
    if ((lane & 3) == 0) {
        rssm[((wid >> 2) << 6) + wq + (lane >> 2)] = rs0;
        rssm[((wid >> 2) << 6) + wq + (lane >> 2) + 8] = rs1;
    }
    __syncthreads();

#pragma unroll
    for (int mt = 0; mt < 4; mt++) {
        int r0 = (mt << 4) + (lane >> 2);
        int r1 = r0 + 8;
        float inv0 = 1.0f / (rssm[r0] + rssm[64 + r0]);
        float inv1 = 1.0f / (rssm[r1] + rssm[64 + r1]);
#pragma unroll
        for (int sub = 0; sub < 2; sub++) {
            int col = (wid << 4) + (sub << 3) + ((lane & 3) << 1);
            float v00 = oacc[mt][sub][0] * inv0;
            float v01 = oacc[mt][sub][1] * inv0;
            float v10 = oacc[mt][sub][2] * inv1;
            float v11 = oacc[mt][sub][3] * inv1;
            size_t base0 = ((size_t)(b * S_LEN + q0 + r0)) * D_MODEL + h * HD_N + col;
            size_t base1 = ((size_t)(b * S_LEN + q0 + r1)) * D_MODEL + h * HD_N + col;
            __nv_bfloat16 h0, l0, h1, l1;
            split1(v00, h0, l0); split1(v01, h1, l1);
            *(__nv_bfloat162*)(Oh + base0) = __nv_bfloat162(h0, h1);
            *(__nv_bfloat162*)(Ol + base0) = __nv_bfloat162(l0, l1);
            split1(v10, h0, l0); split1(v11, h1, l1);
            *(__nv_bfloat162*)(Oh + base1) = __nv_bfloat162(h0, h1);
            *(__nv_bfloat162*)(Ol + base1) = __nv_bfloat162(l0, l1);
        }
    }
}

// ---------------------------------------------------------------------------
// Launch
// ---------------------------------------------------------------------------
extern "C" void kernel_launch(void* const* d_in, const int* in_sizes, int n_in,
                              void* d_out, int out_size) {
    const float* hidden = (const float*)d_in[0];
    const float* cosb   = (const float*)d_in[1];
    const float* sinb   = (const float*)d_in[2];
    const float* Wq     = (const float*)d_in[3];
    const float* Wk     = (const float*)d_in[4];
    const float* Wv     = (const float*)d_in[5];
    const float* Wo     = (const float*)d_in[6];
    float* out = (float*)d_out;

    float *pQ, *pK, *pV;
    cudaGetSymbolAddress((void**)&pQ, g_Q);
    cudaGetSymbolAddress((void**)&pK, g_K);
    cudaGetSymbolAddress((void**)&pV, g_V);

    __nv_bfloat16 *hh, *hl, *qh, *ql, *kh, *kl, *vh, *vl, *oh, *ol, *ah, *al;
    __nv_bfloat16 *pkh, *pkl, *pvh, *pvl;
    cudaGetSymbolAddress((void**)&hh, g_h_hi);  cudaGetSymbolAddress((void**)&hl, g_h_lo);
    cudaGetSymbolAddress((void**)&qh, g_wq_hi); cudaGetSymbolAddress((void**)&ql, g_wq_lo);
    cudaGetSymbolAddress((void**)&kh, g_wk_hi); cudaGetSymbolAddress((void**)&kl, g_wk_lo);
    cudaGetSymbolAddress((void**)&vh, g_wv_hi); cudaGetSymbolAddress((void**)&vl, g_wv_lo);
    cudaGetSymbolAddress((void**)&oh, g_wo_hi); cudaGetSymbolAddress((void**)&ol, g_wo_lo);
    cudaGetSymbolAddress((void**)&ah, g_a_hi);  cudaGetSymbolAddress((void**)&al, g_a_lo);
    cudaGetSymbolAddress((void**)&pkh, g_kh);   cudaGetSymbolAddress((void**)&pkl, g_kl);
    cudaGetSymbolAddress((void**)&pvh, g_vh);   cudaGetSymbolAddress((void**)&pvl, g_vl);

    const int n_big   = 4096 * 4096 / 4;
    const int n_small = 1024 * 4096 / 4;
    split_bf16<<<(n_big + 255) / 256, 256>>>(hidden, hh, hl, n_big);
    split_bf16<<<(n_big + 255) / 256, 256>>>(Wq, qh, ql, n_big);
    split_bf16<<<(n_small + 255) / 256, 256>>>(Wk, kh, kl, n_small);
    split_bf16<<<(n_small + 255) / 256, 256>>>(Wv, vh, vl, n_small);
    split_bf16<<<(n_big + 255) / 256, 256>>>(Wo, oh, ol, n_big);

    cudaFuncSetAttribute(gemm_bf16s, cudaFuncAttributeMaxDynamicSharedMemorySize, SM_GEMM);
    gemm_bf16s<<<dim3(32, 32), 256, SM_GEMM>>>(hh, hl, qh, ql, pQ, 4096);
    gemm_bf16s<<<dim3(8, 32),  256, SM_GEMM>>>(hh, hl, kh, kl, pK, 1024);
    gemm_bf16s<<<dim3(8, 32),  256, SM_GEMM>>>(hh, hl, vh, vl, pV, 1024);

    {
        int tot = MROWS * HKV_N * 64;
        kv_prep<<<(tot + 255) / 256, 256>>>(pK, pV, cosb, sinb, pkh, pkl, pvh, pvl);
    }

    cudaFuncSetAttribute(attn_tc, cudaFuncAttributeMaxDynamicSharedMemorySize, SM_ATTN);
    attn_tc<<<dim3(B_N * HQ_N, S_LEN / 64), 256, SM_ATTN>>>(
        pQ, pkh, pkl, pvh, pvl, cosb, sinb, ah, al);

    gemm_bf16s<<<dim3(32, 32), 256, SM_GEMM>>>(ah, al, oh, ol, out, 4096);
}

// round 9
// speedup vs baseline: 1.1762x; 1.1762x over previous
#include <cuda_runtime.h>
#include <cuda_bf16.h>
#include <math.h>
#include <cstdint>

#define S_LEN   1024
#define B_N     4
#define D_MODEL 4096
#define HQ_N    32
#define HKV_N   8
#define HD_N    128
#define MROWS   4096
#define KDIM    4096
#define ATTN_SCALE 0.08838834764831845f

typedef unsigned long long u64;

__device__ __forceinline__ uint32_t smem_u32(const void* p) {
    uint32_t a;
    asm("{ .reg .u64 t; cvta.to.shared.u64 t, %1; cvt.u32.u64 %0, t; }" : "=r"(a) : "l"(p));
    return a;
}
__device__ __forceinline__ void mma_bf16(float (&d)[4], const uint32_t (&a)[4],
                                         const uint32_t b0, const uint32_t b1) {
    asm volatile(
        "mma.sync.aligned.m16n8k16.row.col.f32.bf16.bf16.f32 "
        "{%0,%1,%2,%3}, {%4,%5,%6,%7}, {%8,%9}, {%0,%1,%2,%3};"
        : "+f"(d[0]), "+f"(d[1]), "+f"(d[2]), "+f"(d[3])
        : "r"(a[0]), "r"(a[1]), "r"(a[2]), "r"(a[3]), "r"(b0), "r"(b1));
}
__device__ __forceinline__ void ldm_x4(uint32_t (&r)[4], uint32_t addr) {
    asm volatile("ldmatrix.sync.aligned.m8n8.x4.shared.b16 {%0,%1,%2,%3}, [%4];"
                 : "=r"(r[0]), "=r"(r[1]), "=r"(r[2]), "=r"(r[3]) : "r"(addr));
}
__device__ __forceinline__ void ldm_x4_t(uint32_t (&r)[4], uint32_t addr) {
    asm volatile("ldmatrix.sync.aligned.m8n8.x4.trans.shared.b16 {%0,%1,%2,%3}, [%4];"
                 : "=r"(r[0]), "=r"(r[1]), "=r"(r[2]), "=r"(r[3]) : "r"(addr));
}
__device__ __forceinline__ void split1(float x, __nv_bfloat16& h, __nv_bfloat16& l) {
    h = __float2bfloat16_rn(x);
    l = __float2bfloat16_rn(x - __bfloat162float(h));
}

// ---------------------------------------------------------------------------
// Scratch
// ---------------------------------------------------------------------------
__device__ float g_Q[(size_t)MROWS * (HQ_N * HD_N)];
__device__ float g_K[(size_t)MROWS * (HKV_N * HD_N)];
__device__ float g_V[(size_t)MROWS * (HKV_N * HD_N)];

__device__ __nv_bfloat16 g_h_hi[(size_t)MROWS * D_MODEL];
__device__ __nv_bfloat16 g_h_lo[(size_t)MROWS * D_MODEL];
__device__ __nv_bfloat16 g_wq_hi[(size_t)4096 * 4096];
__device__ __nv_bfloat16 g_wq_lo[(size_t)4096 * 4096];
__device__ __nv_bfloat16 g_wk_hi[(size_t)1024 * 4096];
__device__ __nv_bfloat16 g_wk_lo[(size_t)1024 * 4096];
__device__ __nv_bfloat16 g_wv_hi[(size_t)1024 * 4096];
__device__ __nv_bfloat16 g_wv_lo[(size_t)1024 * 4096];
__device__ __nv_bfloat16 g_wo_hi[(size_t)4096 * 4096];
__device__ __nv_bfloat16 g_wo_lo[(size_t)4096 * 4096];
__device__ __nv_bfloat16 g_a_hi[(size_t)MROWS * D_MODEL];
__device__ __nv_bfloat16 g_a_lo[(size_t)MROWS * D_MODEL];
__device__ __nv_bfloat16 g_kh[(size_t)MROWS * (HKV_N * HD_N)];
__device__ __nv_bfloat16 g_kl[(size_t)MROWS * (HKV_N * HD_N)];
__device__ __nv_bfloat16 g_vh[(size_t)MROWS * (HKV_N * HD_N)];
__device__ __nv_bfloat16 g_vl[(size_t)MROWS * (HKV_N * HD_N)];

// ---------------------------------------------------------------------------
// fp32 -> bf16 split
// ---------------------------------------------------------------------------
__global__ void split_bf16(const float* __restrict__ X,
                           __nv_bfloat16* __restrict__ H,
                           __nv_bfloat16* __restrict__ L, int n4) {
    int i = blockIdx.x * blockDim.x + threadIdx.x;
    if (i >= n4) return;
    float4 x = *(const float4*)(X + (size_t)i * 4);
    __nv_bfloat16 h0, h1, h2, h3, l0, l1, l2, l3;
    split1(x.x, h0, l0); split1(x.y, h1, l1);
    split1(x.z, h2, l2); split1(x.w, h3, l3);
    __nv_bfloat162* Hp = (__nv_bfloat162*)(H + (size_t)i * 4);
    __nv_bfloat162* Lp = (__nv_bfloat162*)(L + (size_t)i * 4);
    Hp[0] = __nv_bfloat162(h0, h1); Hp[1] = __nv_bfloat162(h2, h3);
    Lp[0] = __nv_bfloat162(l0, l1); Lp[1] = __nv_bfloat162(l2, l3);
}

// ---------------------------------------------------------------------------
// K/V prep: RoPE+split K, split V
// ---------------------------------------------------------------------------
__global__ void kv_prep(const float* __restrict__ K, const float* __restrict__ V,
                        const float* __restrict__ cosb, const float* __restrict__ sinb,
                        __nv_bfloat16* __restrict__ Kh, __nv_bfloat16* __restrict__ Kl,
                        __nv_bfloat16* __restrict__ Vh, __nv_bfloat16* __restrict__ Vl) {
    int idx = blockIdx.x * blockDim.x + threadIdx.x;
    if (idx >= MROWS * HKV_N * 64) return;
    int d = idx & 63;
    int h = (idx >> 6) & 7;
    int bs = idx >> 9;
    int s = bs & (S_LEN - 1);
    float c  = cosb[s * HD_N + 64 + d];
    float sn = sinb[s * HD_N + 64 + d];
    size_t base = (size_t)bs * (HKV_N * HD_N) + h * HD_N + d;
    float x1 = K[base], x2 = K[base + 64];
    float r1 = x1 * c - x2 * sn;
    float r2 = x2 * c + x1 * sn;
    split1(r1, Kh[base], Kl[base]);
    split1(r2, Kh[base + 64], Kl[base + 64]);
    split1(V[base], Vh[base], Vl[base]);
    split1(V[base + 64], Vh[base + 64], Vl[base + 64]);
}

// ---------------------------------------------------------------------------
// bf16-split GEMM via mma.sync: register-staged double buffer, BK=64
// (single change vs R7: BK 32 -> 64, halving barrier/STS-burst count)
// ---------------------------------------------------------------------------
#define SROW   144                 // 64 halves + 8 pad = 144 bytes per row
#define ATILE  (128 * SROW)        // 18432
#define STAGE  (4 * ATILE)         // 73728
#define SM_GEMM (2 * STAGE)        // 147456
#define NCHUNK (KDIM / 64)         // 64

__global__ void __launch_bounds__(256, 1) gemm_bf16s(
    const __nv_bfloat16* __restrict__ A1, const __nv_bfloat16* __restrict__ A2,
    const __nv_bfloat16* __restrict__ B1, const __nv_bfloat16* __restrict__ B2,
    float* __restrict__ C, int Nn) {
    extern __shared__ char smem[];
    const uint32_t smb = smem_u32(smem);
    const int tid = threadIdx.x;
    const int wid = tid >> 5;
    const int lane = tid & 31;
    const int wm = (wid >> 2) << 6;
    const int wn = (wid & 3) << 5;
    const int n0 = blockIdx.x << 7;
    const int m0 = blockIdx.y << 7;

    const __nv_bfloat16* srcs[4] = {
        A1 + (size_t)m0 * KDIM, A2 + (size_t)m0 * KDIM,
        B1 + (size_t)n0 * KDIM, B2 + (size_t)n0 * KDIM };

    // per-thread load slots: 4 per array; slot = tid + i*256
    // row = slot>>3 (0..127), seg = slot&7 (16B units within 64-half row)
    int r_ld[4], sseg[4];
#pragma unroll
    for (int i = 0; i < 4; i++) {
        int slot = tid + (i << 8);
        r_ld[i] = slot >> 3;
        sseg[i] = (slot & 7) << 3;   // halves offset
    }

    float acc[4][4][4];
#pragma unroll
    for (int i = 0; i < 4; i++)
#pragma unroll
        for (int j = 0; j < 4; j++)
#pragma unroll
            for (int t = 0; t < 4; t++) acc[i][j][t] = 0.f;

    // prologue: load chunk 0 into stage 0 (direct, through regs implicitly)
#pragma unroll
    for (int arr = 0; arr < 4; arr++) {
        char* dst = smem + arr * ATILE;
        const __nv_bfloat16* src = srcs[arr];
#pragma unroll
        for (int i = 0; i < 4; i++)
            *(uint4*)(dst + r_ld[i] * SROW + (sseg[i] << 1)) =
                *(const uint4*)(src + (size_t)r_ld[i] * KDIM + sseg[i]);
    }
    __syncthreads();

    const uint32_t a_lrow = (lane & 15);
    const uint32_t a_lkh  = (lane >> 4) << 4;
    const uint32_t b_lrow = (lane & 7) + ((lane >> 4) << 3);
    const uint32_t b_lkh  = ((lane >> 3) & 1) << 4;

    uint4 regs[16];

    for (int c = 0; c < NCHUNK; c++) {
        const int s = c & 1;
        const uint32_t sb = smb + s * STAGE;
        const bool more = (c + 1 < NCHUNK);
        if (more) {
            const int k0 = (c + 1) << 6;
#pragma unroll
            for (int arr = 0; arr < 4; arr++)
#pragma unroll
                for (int i = 0; i < 4; i++)
                    regs[arr * 4 + i] =
                        *(const uint4*)(srcs[arr] + (size_t)r_ld[i] * KDIM + k0 + sseg[i]);
        }

        // compute on stage s: four k16 steps
#pragma unroll
        for (int ks = 0; ks < 4; ks++) {
            const uint32_t ko = ks << 5;   // 32 bytes per k16 step
            uint32_t a1[4][4], a2[4][4];
#pragma unroll
            for (int i = 0; i < 4; i++) {
                uint32_t rowb = (wm + (i << 4) + a_lrow) * SROW + ko + a_lkh;
                ldm_x4(a1[i], sb + 0 * ATILE + rowb);
                ldm_x4(a2[i], sb + 1 * ATILE + rowb);
            }
            uint32_t b1[2][4], b2[2][4];
#pragma unroll
            for (int j2 = 0; j2 < 2; j2++) {
                uint32_t rowb = (wn + (j2 << 4) + b_lrow) * SROW + ko + b_lkh;
                ldm_x4(b1[j2], sb + 2 * ATILE + rowb);
                ldm_x4(b2[j2], sb + 3 * ATILE + rowb);
            }
#pragma unroll
            for (int i = 0; i < 4; i++)
#pragma unroll
                for (int j = 0; j < 4; j++) {
                    const uint32_t* bb1 = &b1[j >> 1][(j & 1) << 1];
                    const uint32_t* bb2 = &b2[j >> 1][(j & 1) << 1];
                    mma_bf16(acc[i][j], a1[i], bb1[0], bb1[1]);
                    mma_bf16(acc[i][j], a1[i], bb2[0], bb2[1]);
                    mma_bf16(acc[i][j], a2[i], bb1[0], bb1[1]);
                }
        }

        if (more) {
            const int so = (s ^ 1) * STAGE;
#pragma unroll
            for (int arr = 0; arr < 4; arr++)
#pragma unroll
                for (int i = 0; i < 4; i++)
                    *(uint4*)(smem + so + arr * ATILE + r_ld[i] * SROW + (sseg[i] << 1)) =
                        regs[arr * 4 + i];
        }
        __syncthreads();
    }

    const int erow = m0 + wm + (lane >> 2);
    const int ecol = n0 + wn + ((lane & 3) << 1);
#pragma unroll
    for (int i = 0; i < 4; i++) {
#pragma unroll
        for (int j = 0; j < 4; j++) {
            float* p0 = C + (size_t)(erow + (i << 4)) * Nn + ecol + (j << 3);
            float* p1 = p0 + (size_t)8 * Nn;
            *(float2*)p0 = make_float2(acc[i][j][0], acc[i][j][1]);
            *(float2*)p1 = make_float2(acc[i][j][2], acc[i][j][3]);
        }
    }
}

// ---------------------------------------------------------------------------
// Tensor-core attention (exact R7 version)
// ---------------------------------------------------------------------------
#define QKV_RS 136
#define P_RS   72
#define SM_QH  0
#define SM_QL  17408
#define SM_KH  34816
#define SM_KL  52224
#define SM_VH  69632
#define SM_VL  87040
#define SM_PH  104448
#define SM_PL  113664
#define SM_RS  122880
#define SM_ATTN (SM_RS + 512)

__global__ void __launch_bounds__(256, 1) attn_tc(
    const float* __restrict__ Q,
    const __nv_bfloat16* __restrict__ Kh, const __nv_bfloat16* __restrict__ Kl,
    const __nv_bfloat16* __restrict__ Vh, const __nv_bfloat16* __restrict__ Vl,
    const float* __restrict__ cosb, const float* __restrict__ sinb,
    __nv_bfloat16* __restrict__ Oh, __nv_bfloat16* __restrict__ Ol) {
    extern __shared__ char smem[];
    const uint32_t smb = smem_u32(smem);
    const int tid = threadIdx.x;
    const int wid = tid >> 5;
    const int lane = tid & 31;
    const int b   = blockIdx.x >> 5;
    const int h   = blockIdx.x & 31;
    const int kvh = h >> 2;
    const int q0  = blockIdx.y << 6;

    const uint32_t a_lrow = (lane & 15);
    const uint32_t a_lkh  = (lane >> 4) << 4;
    const uint32_t b_lrow = (lane & 7) + ((lane >> 4) << 3);
    const uint32_t b_lkh  = ((lane >> 3) & 1) << 4;
    const int wq = (wid & 3) << 4;
    const int wk = (wid >> 2) << 5;

#pragma unroll
    for (int it = 0; it < 4; it++) {
        int slot = tid + (it << 8);
        int r = slot >> 4;
        int d = (slot & 15) << 2;
        int srow = q0 + r;
        const float* src = Q + ((size_t)(b * S_LEN + srow)) * (HQ_N * HD_N) + h * HD_N + d;
        float4 x1 = *(const float4*)(src);
        float4 x2 = *(const float4*)(src + 64);
        float4 cs = *(const float4*)(cosb + srow * HD_N + 64 + d);
        float4 sn = *(const float4*)(sinb + srow * HD_N + 64 + d);
        float o1[4] = { (x1.x * cs.x - x2.x * sn.x) * ATTN_SCALE,
                        (x1.y * cs.y - x2.y * sn.y) * ATTN_SCALE,
                        (x1.z * cs.z - x2.z * sn.z) * ATTN_SCALE,
                        (x1.w * cs.w - x2.w * sn.w) * ATTN_SCALE };
        float o2[4] = { (x2.x * cs.x + x1.x * sn.x) * ATTN_SCALE,
                        (x2.y * cs.y + x1.y * sn.y) * ATTN_SCALE,
                        (x2.z * cs.z + x1.z * sn.z) * ATTN_SCALE,
                        (x2.w * cs.w + x1.w * sn.w) * ATTN_SCALE };
        __nv_bfloat16* qh = (__nv_bfloat16*)(smem + SM_QH) + r * QKV_RS;
        __nv_bfloat16* ql = (__nv_bfloat16*)(smem + SM_QL) + r * QKV_RS;
#pragma unroll
        for (int u = 0; u < 4; u++) {
            split1(o1[u], qh[d + u], ql[d + u]);
            split1(o2[u], qh[d + 64 + u], ql[d + 64 + u]);
        }
    }

    float oacc[4][2][4];
#pragma unroll
    for (int i = 0; i < 4; i++)
#pragma unroll
        for (int j = 0; j < 2; j++)
#pragma unroll
            for (int t = 0; t < 4; t++) oacc[i][j][t] = 0.f;
    float rs0 = 0.f, rs1 = 0.f;

    const __nv_bfloat16* kvsrc[4] = { Kh, Kl, Vh, Vl };
    const uint32_t kvdst[4] = { SM_KH, SM_KL, SM_VH, SM_VL };

    for (int kt = 0; kt < S_LEN; kt += 64) {
        __syncthreads();

#pragma unroll
        for (int arr = 0; arr < 4; arr++) {
            const __nv_bfloat16* src = kvsrc[arr]
                + ((size_t)(b * S_LEN + kt)) * (HKV_N * HD_N) + kvh * HD_N;
            char* dst = smem + kvdst[arr];
#pragma unroll
            for (int it = 0; it < 4; it++) {
                int slot = tid + (it << 8);
                int r = slot >> 4;
                int cs = slot & 15;
                *(uint4*)(dst + r * (QKV_RS * 2) + (cs << 4)) =
                    *(const uint4*)(src + (size_t)r * (HKV_N * HD_N) + (cs << 3));
            }
        }
        __syncthreads();

        float sacc[4][4];
#pragma unroll
        for (int i = 0; i < 4; i++)
#pragma unroll
            for (int t = 0; t < 4; t++) sacc[i][t] = 0.f;

#pragma unroll
        for (int ks = 0; ks < 8; ks++) {
            const uint32_t ko = ks << 5;
            uint32_t ah[4], al[4];
            {
                uint32_t rowb = (wq + a_lrow) * (QKV_RS * 2) + ko + a_lkh;
                ldm_x4(ah, smb + SM_QH + rowb);
                ldm_x4(al, smb + SM_QL + rowb);
            }
            uint32_t bh[2][4], bl[2][4];
#pragma unroll
            for (int g = 0; g < 2; g++) {
                uint32_t rowb = (wk + (g << 4) + b_lrow) * (QKV_RS * 2) + ko + b_lkh;
                ldm_x4(bh[g], smb + SM_KH + rowb);
                ldm_x4(bl[g], smb + SM_KL + rowb);
            }
#pragma unroll
            for (int g = 0; g < 2; g++)
#pragma unroll
                for (int sub = 0; sub < 2; sub++) {
                    int nidx = (g << 1) + sub;
                    const uint32_t* h2 = &bh[g][sub << 1];
                    const uint32_t* l2 = &bl[g][sub << 1];
                    mma_bf16(sacc[nidx], ah, h2[0], h2[1]);
                    mma_bf16(sacc[nidx], ah, l2[0], l2[1]);
                    mma_bf16(sacc[nidx], al, h2[0], h2[1]);
                }
        }

        float ps0 = 0.f, ps1 = 0.f;
        const int prow0 = wq + (lane >> 2);
#pragma unroll
        for (int f = 0; f < 4; f++) {
            float p0 = __expf(sacc[f][0]);
            float p1 = __expf(sacc[f][1]);
            float p2 = __expf(sacc[f][2]);
            float p3 = __expf(sacc[f][3]);
            ps0 += p0 + p1;
            ps1 += p2 + p3;
            int col = wk + (f << 3) + ((lane & 3) << 1);
            __nv_bfloat16 h0, l0, h1, l1;
            split1(p0, h0, l0); split1(p1, h1, l1);
            *(__nv_bfloat162*)((__nv_bfloat16*)(smem + SM_PH) + prow0 * P_RS + col) = __nv_bfloat162(h0, h1);
            *(__nv_bfloat162*)((__nv_bfloat16*)(smem + SM_PL) + prow0 * P_RS + col) = __nv_bfloat162(l0, l1);
            split1(p2, h0, l0); split1(p3, h1, l1);
            *(__nv_bfloat162*)((__nv_bfloat16*)(smem + SM_PH) + (prow0 + 8) * P_RS + col) = __nv_bfloat162(h0, h1);
            *(__nv_bfloat162*)((__nv_bfloat16*)(smem + SM_PL) + (prow0 + 8) * P_RS + col) = __nv_bfloat162(l0, l1);
        }
        ps0 += __shfl_xor_sync(0xFFFFFFFF, ps0, 1);
        ps0 += __shfl_xor_sync(0xFFFFFFFF, ps0, 2);
        ps1 += __shfl_xor_sync(0xFFFFFFFF, ps1, 1);
        ps1 += __shfl_xor_sync(0xFFFFFFFF, ps1, 2);
        rs0 += ps0;
        rs1 += ps1;
        __syncthreads();

        const int nb = wid << 4;
#pragma unroll
        for (int ks = 0; ks < 4; ks++) {
            uint32_t vbh[4], vbl[4];
            {
                uint32_t rowb = ((ks << 4) + (lane & 15)) * (QKV_RS * 2) + ((nb + ((lane >> 4) << 3)) << 1);
                ldm_x4_t(vbh, smb + SM_VH + rowb);
                ldm_x4_t(vbl, smb + SM_VL + rowb);
            }
#pragma unroll
            for (int mt = 0; mt < 4; mt++) {
                uint32_t pah[4], pal[4];
                uint32_t rowb = ((mt << 4) + a_lrow) * (P_RS * 2) + (ks << 5) + a_lkh;
                ldm_x4(pah, smb + SM_PH + rowb);
                ldm_x4(pal, smb + SM_PL + rowb);
#pragma unroll
                for (int sub = 0; sub < 2; sub++) {
                    const uint32_t* h2 = &vbh[sub << 1];
                    const uint32_t* l2 = &vbl[sub << 1];
                    mma_bf16(oacc[mt][sub], pah, h2[0], h2[1]);
                    mma_bf16(oacc[mt][sub], pah, l2[0], l2[1]);
                    mma_bf16(oacc[mt][sub], pal, h2[0], h2[1]);
                }
            }
        }
    }

    float* rssm = (float*)(smem + SM_RS);
    if ((lane & 3) == 0) {
        rssm[((wid >> 2) << 6) + wq + (lane >> 2)] = rs0;
        rssm[((wid >> 2) << 6) + wq + (lane >> 2) + 8] = rs1;
    }
    __syncthreads();

#pragma unroll
    for (int mt = 0; mt < 4; mt++) {
        int r0 = (mt << 4) + (lane >> 2);
        int r1 = r0 + 8;
        float inv0 = 1.0f / (rssm[r0] + rssm[64 + r0]);
        float inv1 = 1.0f / (rssm[r1] + rssm[64 + r1]);
#pragma unroll
        for (int sub = 0; sub < 2; sub++) {
            int col = (wid << 4) + (sub << 3) + ((lane & 3) << 1);
            float v00 = oacc[mt][sub][0] * inv0;
            float v01 = oacc[mt][sub][1] * inv0;
            float v10 = oacc[mt][sub][2] * inv1;
            float v11 = oacc[mt][sub][3] * inv1;
            size_t base0 = ((size_t)(b * S_LEN + q0 + r0)) * D_MODEL + h * HD_N + col;
            size_t base1 = ((size_t)(b * S_LEN + q0 + r1)) * D_MODEL + h * HD_N + col;
            __nv_bfloat16 h0, l0, h1, l1;
            split1(v00, h0, l0); split1(v01, h1, l1);
            *(__nv_bfloat162*)(Oh + base0) = __nv_bfloat162(h0, h1);
            *(__nv_bfloat162*)(Ol + base0) = __nv_bfloat162(l0, l1);
            split1(v10, h0, l0); split1(v11, h1, l1);
            *(__nv_bfloat162*)(Oh + base1) = __nv_bfloat162(h0, h1);
            *(__nv_bfloat162*)(Ol + base1) = __nv_bfloat162(l0, l1);
        }
    }
}

// ---------------------------------------------------------------------------
// Launch
// ---------------------------------------------------------------------------
extern "C" void kernel_launch(void* const* d_in, const int* in_sizes, int n_in,
                              void* d_out, int out_size) {
    const float* hidden = (const float*)d_in[0];
    const float* cosb   = (const float*)d_in[1];
    const float* sinb   = (const float*)d_in[2];
    const float* Wq     = (const float*)d_in[3];
    const float* Wk     = (const float*)d_in[4];
    const float* Wv     = (const float*)d_in[5];
    const float* Wo     = (const float*)d_in[6];
    float* out = (float*)d_out;

    float *pQ, *pK, *pV;
    cudaGetSymbolAddress((void**)&pQ, g_Q);
    cudaGetSymbolAddress((void**)&pK, g_K);
    cudaGetSymbolAddress((void**)&pV, g_V);

    __nv_bfloat16 *hh, *hl, *qh, *ql, *kh, *kl, *vh, *vl, *oh, *ol, *ah, *al;
    __nv_bfloat16 *pkh, *pkl, *pvh, *pvl;
    cudaGetSymbolAddress((void**)&hh, g_h_hi);  cudaGetSymbolAddress((void**)&hl, g_h_lo);
    cudaGetSymbolAddress((void**)&qh, g_wq_hi); cudaGetSymbolAddress((void**)&ql, g_wq_lo);
    cudaGetSymbolAddress((void**)&kh, g_wk_hi); cudaGetSymbolAddress((void**)&kl, g_wk_lo);
    cudaGetSymbolAddress((void**)&vh, g_wv_hi); cudaGetSymbolAddress((void**)&vl, g_wv_lo);
    cudaGetSymbolAddress((void**)&oh, g_wo_hi); cudaGetSymbolAddress((void**)&ol, g_wo_lo);
    cudaGetSymbolAddress((void**)&ah, g_a_hi);  cudaGetSymbolAddress((void**)&al, g_a_lo);
    cudaGetSymbolAddress((void**)&pkh, g_kh);   cudaGetSymbolAddress((void**)&pkl, g_kl);
    cudaGetSymbolAddress((void**)&pvh, g_vh);   cudaGetSymbolAddress((void**)&pvl, g_vl);

    const int n_big   = 4096 * 4096 / 4;
    const int n_small = 1024 * 4096 / 4;
    split_bf16<<<(n_big + 255) / 256, 256>>>(hidden, hh, hl, n_big);
    split_bf16<<<(n_big + 255) / 256, 256>>>(Wq, qh, ql, n_big);
    split_bf16<<<(n_small + 255) / 256, 256>>>(Wk, kh, kl, n_small);
    split_bf16<<<(n_small + 255) / 256, 256>>>(Wv, vh, vl, n_small);
    split_bf16<<<(n_big + 255) / 256, 256>>>(Wo, oh, ol, n_big);

    cudaFuncSetAttribute(gemm_bf16s, cudaFuncAttributeMaxDynamicSharedMemorySize, SM_GEMM);
    gemm_bf16s<<<dim3(32, 32), 256, SM_GEMM>>>(hh, hl, qh, ql, pQ, 4096);
    gemm_bf16s<<<dim3(8, 32),  256, SM_GEMM>>>(hh, hl, kh, kl, pK, 1024);
    gemm_bf16s<<<dim3(8, 32),  256, SM_GEMM>>>(hh, hl, vh, vl, pV, 1024);

    {
        int tot = MROWS * HKV_N * 64;
        kv_prep<<<(tot + 255) / 256, 256>>>(pK, pV, cosb, sinb, pkh, pkl, pvh, pvl);
    }

    cudaFuncSetAttribute(attn_tc, cudaFuncAttributeMaxDynamicSharedMemorySize, SM_ATTN);
    attn_tc<<<dim3(B_N * HQ_N, S_LEN / 64), 256, SM_ATTN>>>(
        pQ, pkh, pkl, pvh, pvl, cosb, sinb, ah, al);

    gemm_bf16s<<<dim3(32, 32), 256, SM_GEMM>>>(ah, al, oh, ol, out, 4096);
}

// round 10
// speedup vs baseline: 1.5281x; 1.2992x over previous
#include <cuda_runtime.h>
#include <cuda_bf16.h>
#include <cuda_fp16.h>
#include <math.h>
#include <cstdint>

#define S_LEN   1024
#define B_N     4
#define D_MODEL 4096
#define HQ_N    32
#define HKV_N   8
#define HD_N    128
#define MROWS   4096
#define KDIM    4096
#define ATTN_SCALE 0.08838834764831845f

typedef unsigned long long u64;

__device__ __forceinline__ uint32_t smem_u32(const void* p) {
    uint32_t a;
    asm("{ .reg .u64 t; cvta.to.shared.u64 t, %1; cvt.u32.u64 %0, t; }" : "=r"(a) : "l"(p));
    return a;
}
__device__ __forceinline__ void mma_bf16(float (&d)[4], const uint32_t (&a)[4],
                                         const uint32_t b0, const uint32_t b1) {
    asm volatile(
        "mma.sync.aligned.m16n8k16.row.col.f32.bf16.bf16.f32 "
        "{%0,%1,%2,%3}, {%4,%5,%6,%7}, {%8,%9}, {%0,%1,%2,%3};"
        : "+f"(d[0]), "+f"(d[1]), "+f"(d[2]), "+f"(d[3])
        : "r"(a[0]), "r"(a[1]), "r"(a[2]), "r"(a[3]), "r"(b0), "r"(b1));
}
__device__ __forceinline__ void mma_f16(float (&d)[4], const uint32_t (&a)[4],
                                        const uint32_t b0, const uint32_t b1) {
    asm volatile(
        "mma.sync.aligned.m16n8k16.row.col.f32.f16.f16.f32 "
        "{%0,%1,%2,%3}, {%4,%5,%6,%7}, {%8,%9}, {%0,%1,%2,%3};"
        : "+f"(d[0]), "+f"(d[1]), "+f"(d[2]), "+f"(d[3])
        : "r"(a[0]), "r"(a[1]), "r"(a[2]), "r"(a[3]), "r"(b0), "r"(b1));
}
__device__ __forceinline__ void ldm_x4(uint32_t (&r)[4], uint32_t addr) {
    asm volatile("ldmatrix.sync.aligned.m8n8.x4.shared.b16 {%0,%1,%2,%3}, [%4];"
                 : "=r"(r[0]), "=r"(r[1]), "=r"(r[2]), "=r"(r[3]) : "r"(addr));
}
__device__ __forceinline__ void ldm_x4_t(uint32_t (&r)[4], uint32_t addr) {
    asm volatile("ldmatrix.sync.aligned.m8n8.x4.trans.shared.b16 {%0,%1,%2,%3}, [%4];"
                 : "=r"(r[0]), "=r"(r[1]), "=r"(r[2]), "=r"(r[3]) : "r"(addr));
}
__device__ __forceinline__ void split1(float x, __nv_bfloat16& h, __nv_bfloat16& l) {
    h = __float2bfloat16_rn(x);
    l = __float2bfloat16_rn(x - __bfloat162float(h));
}
__device__ __forceinline__ void split1h(float x, __half& h, __half& l) {
    h = __float2half_rn(x);
    l = __float2half_rn(x - __half2float(h));
}

// ---------------------------------------------------------------------------
// Scratch
// ---------------------------------------------------------------------------
__device__ float g_Q[(size_t)MROWS * (HQ_N * HD_N)];
__device__ float g_K[(size_t)MROWS * (HKV_N * HD_N)];
__device__ float g_V[(size_t)MROWS * (HKV_N * HD_N)];

// fp16 GEMM operands
__device__ __half g_h_hi[(size_t)MROWS * D_MODEL];
__device__ __half g_h_lo[(size_t)MROWS * D_MODEL];
__device__ __half g_wq[(size_t)4096 * 4096];
__device__ __half g_wk[(size_t)1024 * 4096];
__device__ __half g_wv[(size_t)1024 * 4096];
__device__ __half g_wo[(size_t)4096 * 4096];
__device__ __half g_a_hi[(size_t)MROWS * D_MODEL];
__device__ __half g_a_lo[(size_t)MROWS * D_MODEL];
// pre-split roped K and split V (bf16 hi/lo) for attention
__device__ __nv_bfloat16 g_kh[(size_t)MROWS * (HKV_N * HD_N)];
__device__ __nv_bfloat16 g_kl[(size_t)MROWS * (HKV_N * HD_N)];
__device__ __nv_bfloat16 g_vh[(size_t)MROWS * (HKV_N * HD_N)];
__device__ __nv_bfloat16 g_vl[(size_t)MROWS * (HKV_N * HD_N)];

// ---------------------------------------------------------------------------
// fp32 -> fp16 split-2 (x = hi + lo)
// ---------------------------------------------------------------------------
__global__ void split_f16(const float* __restrict__ X,
                          __half* __restrict__ H,
                          __half* __restrict__ L, int n4) {
    int i = blockIdx.x * blockDim.x + threadIdx.x;
    if (i >= n4) return;
    float4 x = *(const float4*)(X + (size_t)i * 4);
    __half h0, h1, h2, h3, l0, l1, l2, l3;
    split1h(x.x, h0, l0); split1h(x.y, h1, l1);
    split1h(x.z, h2, l2); split1h(x.w, h3, l3);
    __half2* Hp = (__half2*)(H + (size_t)i * 4);
    __half2* Lp = (__half2*)(L + (size_t)i * 4);
    Hp[0] = __half2(h0, h1); Hp[1] = __half2(h2, h3);
    Lp[0] = __half2(l0, l1); Lp[1] = __half2(l2, l3);
}

// fp32 -> fp16 single (weights)
__global__ void conv_f16(const float* __restrict__ X,
                         __half* __restrict__ H, int n4) {
    int i = blockIdx.x * blockDim.x + threadIdx.x;
    if (i >= n4) return;
    float4 x = *(const float4*)(X + (size_t)i * 4);
    __half2* Hp = (__half2*)(H + (size_t)i * 4);
    Hp[0] = __half2(__float2half_rn(x.x), __float2half_rn(x.y));
    Hp[1] = __half2(__float2half_rn(x.z), __float2half_rn(x.w));
}

// ---------------------------------------------------------------------------
// K/V prep: RoPE+split K, split V (bf16, for split-3 attention)
// ---------------------------------------------------------------------------
__global__ void kv_prep(const float* __restrict__ K, const float* __restrict__ V,
                        const float* __restrict__ cosb, const float* __restrict__ sinb,
                        __nv_bfloat16* __restrict__ Kh, __nv_bfloat16* __restrict__ Kl,
                        __nv_bfloat16* __restrict__ Vh, __nv_bfloat16* __restrict__ Vl) {
    int idx = blockIdx.x * blockDim.x + threadIdx.x;
    if (idx >= MROWS * HKV_N * 64) return;
    int d = idx & 63;
    int h = (idx >> 6) & 7;
    int bs = idx >> 9;
    int s = bs & (S_LEN - 1);
    float c  = cosb[s * HD_N + 64 + d];
    float sn = sinb[s * HD_N + 64 + d];
    size_t base = (size_t)bs * (HKV_N * HD_N) + h * HD_N + d;
    float x1 = K[base], x2 = K[base + 64];
    float r1 = x1 * c - x2 * sn;
    float r2 = x2 * c + x1 * sn;
    split1(r1, Kh[base], Kl[base]);
    split1(r2, Kh[base + 64], Kl[base + 64]);
    split1(V[base], Vh[base], Vl[base]);
    split1(V[base + 64], Vh[base + 64], Vl[base + 64]);
}

// ---------------------------------------------------------------------------
// fp16 2-product GEMM via mma.sync: C = (A1+A2)[M][K] * B[N][K]^T
// register-staged double buffer, BK=64, 3 SMEM arrays (A1,A2,B)
// ---------------------------------------------------------------------------
#define SROW   144                 // 64 halves + 8 pad = 144 bytes per row
#define ATILE  (128 * SROW)        // 18432
#define STAGE  (3 * ATILE)         // 55296
#define SM_GEMM (2 * STAGE)        // 110592
#define NCHUNK (KDIM / 64)         // 64

__global__ void __launch_bounds__(256, 1) gemm_f16x2(
    const __half* __restrict__ A1, const __half* __restrict__ A2,
    const __half* __restrict__ B,
    float* __restrict__ C, int Nn) {
    extern __shared__ char smem[];
    const uint32_t smb = smem_u32(smem);
    const int tid = threadIdx.x;
    const int wid = tid >> 5;
    const int lane = tid & 31;
    const int wm = (wid >> 2) << 6;
    const int wn = (wid & 3) << 5;
    const int n0 = blockIdx.x << 7;
    const int m0 = blockIdx.y << 7;

    const __half* srcs[3] = {
        A1 + (size_t)m0 * KDIM, A2 + (size_t)m0 * KDIM,
        B + (size_t)n0 * KDIM };

    int r_ld[4], sseg[4];
#pragma unroll
    for (int i = 0; i < 4; i++) {
        int slot = tid + (i << 8);
        r_ld[i] = slot >> 3;
        sseg[i] = (slot & 7) << 3;   // halves offset
    }

    float acc[4][4][4];
#pragma unroll
    for (int i = 0; i < 4; i++)
#pragma unroll
        for (int j = 0; j < 4; j++)
#pragma unroll
            for (int t = 0; t < 4; t++) acc[i][j][t] = 0.f;

    // prologue: chunk 0 -> stage 0
#pragma unroll
    for (int arr = 0; arr < 3; arr++) {
        char* dst = smem + arr * ATILE;
        const __half* src = srcs[arr];
#pragma unroll
        for (int i = 0; i < 4; i++)
            *(uint4*)(dst + r_ld[i] * SROW + (sseg[i] << 1)) =
                *(const uint4*)(src + (size_t)r_ld[i] * KDIM + sseg[i]);
    }
    __syncthreads();

    const uint32_t a_lrow = (lane & 15);
    const uint32_t a_lkh  = (lane >> 4) << 4;
    const uint32_t b_lrow = (lane & 7) + ((lane >> 4) << 3);
    const uint32_t b_lkh  = ((lane >> 3) & 1) << 4;

    uint4 regs[12];

    for (int c = 0; c < NCHUNK; c++) {
        const int s = c & 1;
        const uint32_t sb = smb + s * STAGE;
        const bool more = (c + 1 < NCHUNK);
        if (more) {
            const int k0 = (c + 1) << 6;
#pragma unroll
            for (int arr = 0; arr < 3; arr++)
#pragma unroll
                for (int i = 0; i < 4; i++)
                    regs[arr * 4 + i] =
                        *(const uint4*)(srcs[arr] + (size_t)r_ld[i] * KDIM + k0 + sseg[i]);
        }

#pragma unroll
        for (int ks = 0; ks < 4; ks++) {
            const uint32_t ko = ks << 5;
            uint32_t a1[4][4], a2[4][4];
#pragma unroll
            for (int i = 0; i < 4; i++) {
                uint32_t rowb = (wm + (i << 4) + a_lrow) * SROW + ko + a_lkh;
                ldm_x4(a1[i], sb + 0 * ATILE + rowb);
                ldm_x4(a2[i], sb + 1 * ATILE + rowb);
            }
            uint32_t bf[2][4];
#pragma unroll
            for (int j2 = 0; j2 < 2; j2++) {
                uint32_t rowb = (wn + (j2 << 4) + b_lrow) * SROW + ko + b_lkh;
                ldm_x4(bf[j2], sb + 2 * ATILE + rowb);
            }
#pragma unroll
            for (int i = 0; i < 4; i++)
#pragma unroll
                for (int j = 0; j < 4; j++) {
                    const uint32_t* bb = &bf[j >> 1][(j & 1) << 1];
                    mma_f16(acc[i][j], a1[i], bb[0], bb[1]);
                    mma_f16(acc[i][j], a2[i], bb[0], bb[1]);
                }
        }

        if (more) {
            const int so = (s ^ 1) * STAGE;
#pragma unroll
            for (int arr = 0; arr < 3; arr++)
#pragma unroll
                for (int i = 0; i < 4; i++)
                    *(uint4*)(smem + so + arr * ATILE + r_ld[i] * SROW + (sseg[i] << 1)) =
                        regs[arr * 4 + i];
        }
        __syncthreads();
    }

    const int erow = m0 + wm + (lane >> 2);
    const int ecol = n0 + wn + ((lane & 3) << 1);
#pragma unroll
    for (int i = 0; i < 4; i++) {
#pragma unroll
        for (int j = 0; j < 4; j++) {
            float* p0 = C + (size_t)(erow + (i << 4)) * Nn + ecol + (j << 3);
            float* p1 = p0 + (size_t)8 * Nn;
            *(float2*)p0 = make_float2(acc[i][j][0], acc[i][j][1]);
            *(float2*)p1 = make_float2(acc[i][j][2], acc[i][j][3]);
        }
    }
}

// ---------------------------------------------------------------------------
// Tensor-core attention (bf16 split-3, unchanged except fp16 split-2 output)
// ---------------------------------------------------------------------------
#define QKV_RS 136
#define P_RS   72
#define SM_QH  0
#define SM_QL  17408
#define SM_KH  34816
#define SM_KL  52224
#define SM_VH  69632
#define SM_VL  87040
#define SM_PH  104448
#define SM_PL  113664
#define SM_RS  122880
#define SM_ATTN (SM_RS + 512)

__global__ void __launch_bounds__(256, 1) attn_tc(
    const float* __restrict__ Q,
    const __nv_bfloat16* __restrict__ Kh, const __nv_bfloat16* __restrict__ Kl,
    const __nv_bfloat16* __restrict__ Vh, const __nv_bfloat16* __restrict__ Vl,
    const float* __restrict__ cosb, const float* __restrict__ sinb,
    __half* __restrict__ Oh, __half* __restrict__ Ol) {
    extern __shared__ char smem[];
    const uint32_t smb = smem_u32(smem);
    const int tid = threadIdx.x;
    const int wid = tid >> 5;
    const int lane = tid & 31;
    const int b   = blockIdx.x >> 5;
    const int h   = blockIdx.x & 31;
    const int kvh = h >> 2;
    const int q0  = blockIdx.y << 6;

    const uint32_t a_lrow = (lane & 15);
    const uint32_t a_lkh  = (lane >> 4) << 4;
    const uint32_t b_lrow = (lane & 7) + ((lane >> 4) << 3);
    const uint32_t b_lkh  = ((lane >> 3) & 1) << 4;
    const int wq = (wid & 3) << 4;
    const int wk = (wid >> 2) << 5;

#pragma unroll
    for (int it = 0; it < 4; it++) {
        int slot = tid + (it << 8);
        int r = slot >> 4;
        int d = (slot & 15) << 2;
        int srow = q0 + r;
        const float* src = Q + ((size_t)(b * S_LEN + srow)) * (HQ_N * HD_N) + h * HD_N + d;
        float4 x1 = *(const float4*)(src);
        float4 x2 = *(const float4*)(src + 64);
        float4 cs = *(const float4*)(cosb + srow * HD_N + 64 + d);
        float4 sn = *(const float4*)(sinb + srow * HD_N + 64 + d);
        float o1[4] = { (x1.x * cs.x - x2.x * sn.x) * ATTN_SCALE,
                        (x1.y * cs.y - x2.y * sn.y) * ATTN_SCALE,
                        (x1.z * cs.z - x2.z * sn.z) * ATTN_SCALE,
                        (x1.w * cs.w - x2.w * sn.w) * ATTN_SCALE };
        float o2[4] = { (x2.x * cs.x + x1.x * sn.x) * ATTN_SCALE,
                        (x2.y * cs.y + x1.y * sn.y) * ATTN_SCALE,
                        (x2.z * cs.z + x1.z * sn.z) * ATTN_SCALE,
                        (x2.w * cs.w + x1.w * sn.w) * ATTN_SCALE };
        __nv_bfloat16* qh = (__nv_bfloat16*)(smem + SM_QH) + r * QKV_RS;
        __nv_bfloat16* ql = (__nv_bfloat16*)(smem + SM_QL) + r * QKV_RS;
#pragma unroll
        for (int u = 0; u < 4; u++) {
            split1(o1[u], qh[d + u], ql[d + u]);
            split1(o2[u], qh[d + 64 + u], ql[d + 64 + u]);
        }
    }

    float oacc[4][2][4];
#pragma unroll
    for (int i = 0; i < 4; i++)
#pragma unroll
        for (int j = 0; j < 2; j++)
#pragma unroll
            for (int t = 0; t < 4; t++) oacc[i][j][t] = 0.f;
    float rs0 = 0.f, rs1 = 0.f;

    const __nv_bfloat16* kvsrc[4] = { Kh, Kl, Vh, Vl };
    const uint32_t kvdst[4] = { SM_KH, SM_KL, SM_VH, SM_VL };

    for (int kt = 0; kt < S_LEN; kt += 64) {
        __syncthreads();

#pragma unroll
        for (int arr = 0; arr < 4; arr++) {
            const __nv_bfloat16* src = kvsrc[arr]
                + ((size_t)(b * S_LEN + kt)) * (HKV_N * HD_N) + kvh * HD_N;
            char* dst = smem + kvdst[arr];
#pragma unroll
            for (int it = 0; it < 4; it++) {
                int slot = tid + (it << 8);
                int r = slot >> 4;
                int cs = slot & 15;
                *(uint4*)(dst + r * (QKV_RS * 2) + (cs << 4)) =
                    *(const uint4*)(src + (size_t)r * (HKV_N * HD_N) + (cs << 3));
            }
        }
        __syncthreads();

        float sacc[4][4];
#pragma unroll
        for (int i = 0; i < 4; i++)
#pragma unroll
            for (int t = 0; t < 4; t++) sacc[i][t] = 0.f;

#pragma unroll
        for (int ks = 0; ks < 8; ks++) {
            const uint32_t ko = ks << 5;
            uint32_t ah[4], al[4];
            {
                uint32_t rowb = (wq + a_lrow) * (QKV_RS * 2) + ko + a_lkh;
                ldm_x4(ah, smb + SM_QH + rowb);
                ldm_x4(al, smb + SM_QL + rowb);
            }
            uint32_t bh[2][4], bl[2][4];
#pragma unroll
            for (int g = 0; g < 2; g++) {
                uint32_t rowb = (wk + (g << 4) + b_lrow) * (QKV_RS * 2) + ko + b_lkh;
                ldm_x4(bh[g], smb + SM_KH + rowb);
                ldm_x4(bl[g], smb + SM_KL + rowb);
            }
#pragma unroll
            for (int g = 0; g < 2; g++)
#pragma unroll
                for (int sub = 0; sub < 2; sub++) {
                    int nidx = (g << 1) + sub;
                    const uint32_t* h2 = &bh[g][sub << 1];
                    const uint32_t* l2 = &bl[g][sub << 1];
                    mma_bf16(sacc[nidx], ah, h2[0], h2[1]);
                    mma_bf16(sacc[nidx], ah, l2[0], l2[1]);
                    mma_bf16(sacc[nidx], al, h2[0], h2[1]);
                }
        }

        float ps0 = 0.f, ps1 = 0.f;
        const int prow0 = wq + (lane >> 2);
#pragma unroll
        for (int f = 0; f < 4; f++) {
            float p0 = __expf(sacc[f][0]);
            float p1 = __expf(sacc[f][1]);
            float p2 = __expf(sacc[f][2]);
            float p3 = __expf(sacc[f][3]);
            ps0 += p0 + p1;
            ps1 += p2 + p3;
            int col = wk + (f << 3) + ((lane & 3) << 1);
            __nv_bfloat16 h0, l0, h1, l1;
            split1(p0, h0, l0); split1(p1, h1, l1);
            *(__nv_bfloat162*)((__nv_bfloat16*)(smem + SM_PH) + prow0 * P_RS + col) = __nv_bfloat162(h0, h1);
            *(__nv_bfloat162*)((__nv_bfloat16*)(smem + SM_PL) + prow0 * P_RS + col) = __nv_bfloat162(l0, l1);
            split1(p2, h0, l0); split1(p3, h1, l1);
            *(__nv_bfloat162*)((__nv_bfloat16*)(smem + SM_PH) + (prow0 + 8) * P_RS + col) = __nv_bfloat162(h0, h1);
            *(__nv_bfloat162*)((__nv_bfloat16*)(smem + SM_PL) + (prow0 + 8) * P_RS + col) = __nv_bfloat162(l0, l1);
        }
        ps0 += __shfl_xor_sync(0xFFFFFFFF, ps0, 1);
        ps0 += __shfl_xor_sync(0xFFFFFFFF, ps0, 2);
        ps1 += __shfl_xor_sync(0xFFFFFFFF, ps1, 1);
        ps1 += __shfl_xor_sync(0xFFFFFFFF, ps1, 2);
        rs0 += ps0;
        rs1 += ps1;
        __syncthreads();

        const int nb = wid << 4;
#pragma unroll
        for (int ks = 0; ks < 4; ks++) {
            uint32_t vbh[4], vbl[4];
            {
                uint32_t rowb = ((ks << 4) + (lane & 15)) * (QKV_RS * 2) + ((nb + ((lane >> 4) << 3)) << 1);
                ldm_x4_t(vbh, smb + SM_VH + rowb);
                ldm_x4_t(vbl, smb + SM_VL + rowb);
            }
#pragma unroll
            for (int mt = 0; mt < 4; mt++) {
                uint32_t pah[4], pal[4];
                uint32_t rowb = ((mt << 4) + a_lrow) * (P_RS * 2) + (ks << 5) + a_lkh;
                ldm_x4(pah, smb + SM_PH + rowb);
                ldm_x4(pal, smb + SM_PL + rowb);
#pragma unroll
                for (int sub = 0; sub < 2; sub++) {
                    const uint32_t* h2 = &vbh[sub << 1];
                    const uint32_t* l2 = &vbl[sub << 1];
                    mma_bf16(oacc[mt][sub], pah, h2[0], h2[1]);
                    mma_bf16(oacc[mt][sub], pah, l2[0], l2[1]);
                    mma_bf16(oacc[mt][sub], pal, h2[0], h2[1]);
                }
            }
        }
    }

    float* rssm = (float*)(smem + SM_RS);
    if ((lane & 3) == 0) {
        rssm[((wid >> 2) << 6) + wq + (lane >> 2)] = rs0;
        rssm[((wid >> 2) << 6) + wq + (lane >> 2) + 8] = rs1;
    }
    __syncthreads();

#pragma unroll
    for (int mt = 0; mt < 4; mt++) {
        int r0 = (mt << 4) + (lane >> 2);
        int r1 = r0 + 8;
        float inv0 = 1.0f / (rssm[r0] + rssm[64 + r0]);
        float inv1 = 1.0f / (rssm[r1] + rssm[64 + r1]);
#pragma unroll
        for (int sub = 0; sub < 2; sub++) {
            int col = (wid << 4) + (sub << 3) + ((lane & 3) << 1);
            float v00 = oacc[mt][sub][0] * inv0;
            float v01 = oacc[mt][sub][1] * inv0;
            float v10 = oacc[mt][sub][2] * inv1;
            float v11 = oacc[mt][sub][3] * inv1;
            size_t base0 = ((size_t)(b * S_LEN + q0 + r0)) * D_MODEL + h * HD_N + col;
            size_t base1 = ((size_t)(b * S_LEN + q0 + r1)) * D_MODEL + h * HD_N + col;
            __half h0, l0, h1, l1;
            split1h(v00, h0, l0); split1h(v01, h1, l1);
            *(__half2*)(Oh + base0) = __half2(h0, h1);
            *(__half2*)(Ol + base0) = __half2(l0, l1);
            split1h(v10, h0, l0); split1h(v11, h1, l1);
            *(__half2*)(Oh + base1) = __half2(h0, h1);
            *(__half2*)(Ol + base1) = __half2(l0, l1);
        }
    }
}

// ---------------------------------------------------------------------------
// Launch
// ---------------------------------------------------------------------------
extern "C" void kernel_launch(void* const* d_in, const int* in_sizes, int n_in,
                              void* d_out, int out_size) {
    const float* hidden = (const float*)d_in[0];
    const float* cosb   = (const float*)d_in[1];
    const float* sinb   = (const float*)d_in[2];
    const float* Wq     = (const float*)d_in[3];
    const float* Wk     = (const float*)d_in[4];
    const float* Wv     = (const float*)d_in[5];
    const float* Wo     = (const float*)d_in[6];
    float* out = (float*)d_out;

    float *pQ, *pK, *pV;
    cudaGetSymbolAddress((void**)&pQ, g_Q);
    cudaGetSymbolAddress((void**)&pK, g_K);
    cudaGetSymbolAddress((void**)&pV, g_V);

    __half *hh, *hl, *wq, *wk, *wv, *wo, *ah, *al;
    __nv_bfloat16 *pkh, *pkl, *pvh, *pvl;
    cudaGetSymbolAddress((void**)&hh, g_h_hi); cudaGetSymbolAddress((void**)&hl, g_h_lo);
    cudaGetSymbolAddress((void**)&wq, g_wq);   cudaGetSymbolAddress((void**)&wk, g_wk);
    cudaGetSymbolAddress((void**)&wv, g_wv);   cudaGetSymbolAddress((void**)&wo, g_wo);
    cudaGetSymbolAddress((void**)&ah, g_a_hi); cudaGetSymbolAddress((void**)&al, g_a_lo);
    cudaGetSymbolAddress((void**)&pkh, g_kh);  cudaGetSymbolAddress((void**)&pkl, g_kl);
    cudaGetSymbolAddress((void**)&pvh, g_vh);  cudaGetSymbolAddress((void**)&pvl, g_vl);

    const int n_big   = 4096 * 4096 / 4;
    const int n_small = 1024 * 4096 / 4;
    split_f16<<<(n_big + 255) / 256, 256>>>(hidden, hh, hl, n_big);
    conv_f16<<<(n_big + 255) / 256, 256>>>(Wq, wq, n_big);
    conv_f16<<<(n_small + 255) / 256, 256>>>(Wk, wk, n_small);
    conv_f16<<<(n_small + 255) / 256, 256>>>(Wv, wv, n_small);
    conv_f16<<<(n_big + 255) / 256, 256>>>(Wo, wo, n_big);

    cudaFuncSetAttribute(gemm_f16x2, cudaFuncAttributeMaxDynamicSharedMemorySize, SM_GEMM);
    gemm_f16x2<<<dim3(32, 32), 256, SM_GEMM>>>(hh, hl, wq, pQ, 4096);
    gemm_f16x2<<<dim3(8, 32),  256, SM_GEMM>>>(hh, hl, wk, pK, 1024);
    gemm_f16x2<<<dim3(8, 32),  256, SM_GEMM>>>(hh, hl, wv, pV, 1024);

    {
        int tot = MROWS * HKV_N * 64;
        kv_prep<<<(tot + 255) / 256, 256>>>(pK, pV, cosb, sinb, pkh, pkl, pvh, pvl);
    }

    cudaFuncSetAttribute(attn_tc, cudaFuncAttributeMaxDynamicSharedMemorySize, SM_ATTN);
    attn_tc<<<dim3(B_N * HQ_N, S_LEN / 64), 256, SM_ATTN>>>(
        pQ, pkh, pkl, pvh, pvl, cosb, sinb, ah, al);

    gemm_f16x2<<<dim3(32, 32), 256, SM_GEMM>>>(ah, al, wo, out, 4096);
}

// round 11
// speedup vs baseline: 1.6553x; 1.0833x over previous
#include <cuda_runtime.h>
#include <cuda_bf16.h>
#include <cuda_fp16.h>
#include <math.h>
#include <cstdint>

#define S_LEN   1024
#define B_N     4
#define D_MODEL 4096
#define HQ_N    32
#define HKV_N   8
#define HD_N    128
#define MROWS   4096
#define KDIM    4096
#define ATTN_SCALE 0.08838834764831845f

typedef unsigned long long u64;

__device__ __forceinline__ uint32_t smem_u32(const void* p) {
    uint32_t a;
    asm("{ .reg .u64 t; cvta.to.shared.u64 t, %1; cvt.u32.u64 %0, t; }" : "=r"(a) : "l"(p));
    return a;
}
__device__ __forceinline__ void mma_f16(float (&d)[4], const uint32_t (&a)[4],
                                        const uint32_t b0, const uint32_t b1) {
    asm volatile(
        "mma.sync.aligned.m16n8k16.row.col.f32.f16.f16.f32 "
        "{%0,%1,%2,%3}, {%4,%5,%6,%7}, {%8,%9}, {%0,%1,%2,%3};"
        : "+f"(d[0]), "+f"(d[1]), "+f"(d[2]), "+f"(d[3])
        : "r"(a[0]), "r"(a[1]), "r"(a[2]), "r"(a[3]), "r"(b0), "r"(b1));
}
__device__ __forceinline__ void ldm_x4(uint32_t (&r)[4], uint32_t addr) {
    asm volatile("ldmatrix.sync.aligned.m8n8.x4.shared.b16 {%0,%1,%2,%3}, [%4];"
                 : "=r"(r[0]), "=r"(r[1]), "=r"(r[2]), "=r"(r[3]) : "r"(addr));
}
__device__ __forceinline__ void ldm_x4_t(uint32_t (&r)[4], uint32_t addr) {
    asm volatile("ldmatrix.sync.aligned.m8n8.x4.trans.shared.b16 {%0,%1,%2,%3}, [%4];"
                 : "=r"(r[0]), "=r"(r[1]), "=r"(r[2]), "=r"(r[3]) : "r"(addr));
}
__device__ __forceinline__ void split1h(float x, __half& h, __half& l) {
    h = __float2half_rn(x);
    l = __float2half_rn(x - __half2float(h));
}

// ---------------------------------------------------------------------------
// Scratch
// ---------------------------------------------------------------------------
__device__ float g_Q[(size_t)MROWS * (HQ_N * HD_N)];
__device__ float g_K[(size_t)MROWS * (HKV_N * HD_N)];
__device__ float g_V[(size_t)MROWS * (HKV_N * HD_N)];

__device__ __half g_h_hi[(size_t)MROWS * D_MODEL];
__device__ __half g_h_lo[(size_t)MROWS * D_MODEL];
__device__ __half g_wq[(size_t)4096 * 4096];
__device__ __half g_wk[(size_t)1024 * 4096];
__device__ __half g_wv[(size_t)1024 * 4096];
__device__ __half g_wo[(size_t)4096 * 4096];
__device__ __half g_a_hi[(size_t)MROWS * D_MODEL];
__device__ __half g_a_lo[(size_t)MROWS * D_MODEL];
// single fp16 roped K and fp16 V for attention
__device__ __half g_kf[(size_t)MROWS * (HKV_N * HD_N)];
__device__ __half g_vf[(size_t)MROWS * (HKV_N * HD_N)];

// ---------------------------------------------------------------------------
// fp32 -> fp16 split-2
// ---------------------------------------------------------------------------
__global__ void split_f16(const float* __restrict__ X,
                          __half* __restrict__ H,
                          __half* __restrict__ L, int n4) {
    int i = blockIdx.x * blockDim.x + threadIdx.x;
    if (i >= n4) return;
    float4 x = *(const float4*)(X + (size_t)i * 4);
    __half h0, h1, h2, h3, l0, l1, l2, l3;
    split1h(x.x, h0, l0); split1h(x.y, h1, l1);
    split1h(x.z, h2, l2); split1h(x.w, h3, l3);
    __half2* Hp = (__half2*)(H + (size_t)i * 4);
    __half2* Lp = (__half2*)(L + (size_t)i * 4);
    Hp[0] = __half2(h0, h1); Hp[1] = __half2(h2, h3);
    Lp[0] = __half2(l0, l1); Lp[1] = __half2(l2, l3);
}

// fp32 -> fp16 single
__global__ void conv_f16(const float* __restrict__ X,
                         __half* __restrict__ H, int n4) {
    int i = blockIdx.x * blockDim.x + threadIdx.x;
    if (i >= n4) return;
    float4 x = *(const float4*)(X + (size_t)i * 4);
    __half2* Hp = (__half2*)(H + (size_t)i * 4);
    Hp[0] = __half2(__float2half_rn(x.x), __float2half_rn(x.y));
    Hp[1] = __half2(__float2half_rn(x.z), __float2half_rn(x.w));
}

// ---------------------------------------------------------------------------
// K/V prep: RoPE K -> fp16 single, V -> fp16 single
// ---------------------------------------------------------------------------
__global__ void kv_prep(const float* __restrict__ K, const float* __restrict__ V,
                        const float* __restrict__ cosb, const float* __restrict__ sinb,
                        __half* __restrict__ Kf, __half* __restrict__ Vf) {
    int idx = blockIdx.x * blockDim.x + threadIdx.x;
    if (idx >= MROWS * HKV_N * 64) return;
    int d = idx & 63;
    int h = (idx >> 6) & 7;
    int bs = idx >> 9;
    int s = bs & (S_LEN - 1);
    float c  = cosb[s * HD_N + 64 + d];
    float sn = sinb[s * HD_N + 64 + d];
    size_t base = (size_t)bs * (HKV_N * HD_N) + h * HD_N + d;
    float x1 = K[base], x2 = K[base + 64];
    Kf[base]      = __float2half_rn(x1 * c - x2 * sn);
    Kf[base + 64] = __float2half_rn(x2 * c + x1 * sn);
    Vf[base]      = __float2half_rn(V[base]);
    Vf[base + 64] = __float2half_rn(V[base + 64]);
}

// ---------------------------------------------------------------------------
// fp16 2-product GEMM (unchanged from R10)
// ---------------------------------------------------------------------------
#define SROW   144
#define ATILE  (128 * SROW)
#define STAGE  (3 * ATILE)
#define SM_GEMM (2 * STAGE)
#define NCHUNK (KDIM / 64)

__global__ void __launch_bounds__(256, 1) gemm_f16x2(
    const __half* __restrict__ A1, const __half* __restrict__ A2,
    const __half* __restrict__ B,
    float* __restrict__ C, int Nn) {
    extern __shared__ char smem[];
    const uint32_t smb = smem_u32(smem);
    const int tid = threadIdx.x;
    const int wid = tid >> 5;
    const int lane = tid & 31;
    const int wm = (wid >> 2) << 6;
    const int wn = (wid & 3) << 5;
    const int n0 = blockIdx.x << 7;
    const int m0 = blockIdx.y << 7;

    const __half* srcs[3] = {
        A1 + (size_t)m0 * KDIM, A2 + (size_t)m0 * KDIM,
        B + (size_t)n0 * KDIM };

    int r_ld[4], sseg[4];
#pragma unroll
    for (int i = 0; i < 4; i++) {
        int slot = tid + (i << 8);
        r_ld[i] = slot >> 3;
        sseg[i] = (slot & 7) << 3;
    }

    float acc[4][4][4];
#pragma unroll
    for (int i = 0; i < 4; i++)
#pragma unroll
        for (int j = 0; j < 4; j++)
#pragma unroll
            for (int t = 0; t < 4; t++) acc[i][j][t] = 0.f;

#pragma unroll
    for (int arr = 0; arr < 3; arr++) {
        char* dst = smem + arr * ATILE;
        const __half* src = srcs[arr];
#pragma unroll
        for (int i = 0; i < 4; i++)
            *(uint4*)(dst + r_ld[i] * SROW + (sseg[i] << 1)) =
                *(const uint4*)(src + (size_t)r_ld[i] * KDIM + sseg[i]);
    }
    __syncthreads();

    const uint32_t a_lrow = (lane & 15);
    const uint32_t a_lkh  = (lane >> 4) << 4;
    const uint32_t b_lrow = (lane & 7) + ((lane >> 4) << 3);
    const uint32_t b_lkh  = ((lane >> 3) & 1) << 4;

    uint4 regs[12];

    for (int c = 0; c < NCHUNK; c++) {
        const int s = c & 1;
        const uint32_t sb = smb + s * STAGE;
        const bool more = (c + 1 < NCHUNK);
        if (more) {
            const int k0 = (c + 1) << 6;
#pragma unroll
            for (int arr = 0; arr < 3; arr++)
#pragma unroll
                for (int i = 0; i < 4; i++)
                    regs[arr * 4 + i] =
                        *(const uint4*)(srcs[arr] + (size_t)r_ld[i] * KDIM + k0 + sseg[i]);
        }

#pragma unroll
        for (int ks = 0; ks < 4; ks++) {
            const uint32_t ko = ks << 5;
            uint32_t a1[4][4], a2[4][4];
#pragma unroll
            for (int i = 0; i < 4; i++) {
                uint32_t rowb = (wm + (i << 4) + a_lrow) * SROW + ko + a_lkh;
                ldm_x4(a1[i], sb + 0 * ATILE + rowb);
                ldm_x4(a2[i], sb + 1 * ATILE + rowb);
            }
            uint32_t bf[2][4];
#pragma unroll
            for (int j2 = 0; j2 < 2; j2++) {
                uint32_t rowb = (wn + (j2 << 4) + b_lrow) * SROW + ko + b_lkh;
                ldm_x4(bf[j2], sb + 2 * ATILE + rowb);
            }
#pragma unroll
            for (int i = 0; i < 4; i++)
#pragma unroll
                for (int j = 0; j < 4; j++) {
                    const uint32_t* bb = &bf[j >> 1][(j & 1) << 1];
                    mma_f16(acc[i][j], a1[i], bb[0], bb[1]);
                    mma_f16(acc[i][j], a2[i], bb[0], bb[1]);
                }
        }

        if (more) {
            const int so = (s ^ 1) * STAGE;
#pragma unroll
            for (int arr = 0; arr < 3; arr++)
#pragma unroll
                for (int i = 0; i < 4; i++)
                    *(uint4*)(smem + so + arr * ATILE + r_ld[i] * SROW + (sseg[i] << 1)) =
                        regs[arr * 4 + i];
        }
        __syncthreads();
    }

    const int erow = m0 + wm + (lane >> 2);
    const int ecol = n0 + wn + ((lane & 3) << 1);
#pragma unroll
    for (int i = 0; i < 4; i++) {
#pragma unroll
        for (int j = 0; j < 4; j++) {
            float* p0 = C + (size_t)(erow + (i << 4)) * Nn + ecol + (j << 3);
            float* p1 = p0 + (size_t)8 * Nn;
            *(float2*)p0 = make_float2(acc[i][j][0], acc[i][j][1]);
            *(float2*)p1 = make_float2(acc[i][j][2], acc[i][j][3]);
        }
    }
}

// ---------------------------------------------------------------------------
// Tensor-core attention: fp16 asymmetric.
// QK: Q split-2 x K single (2 mma). PV: P split-2 x V single (2 mma).
// K/V: single fp16 arrays (half the copy traffic of R10).
// ---------------------------------------------------------------------------
#define QKV_RS 136              // halves (272 B rows)
#define P_RS   72
#define SM_QH  0
#define SM_QL  17408
#define SM_KF  34816
#define SM_VF  52224
#define SM_PH  69632
#define SM_PL  78848
#define SM_RS  88064
#define SM_ATTN (SM_RS + 512)

__global__ void __launch_bounds__(256, 1) attn_tc(
    const float* __restrict__ Q,
    const __half* __restrict__ Kf, const __half* __restrict__ Vf,
    const float* __restrict__ cosb, const float* __restrict__ sinb,
    __half* __restrict__ Oh, __half* __restrict__ Ol) {
    extern __shared__ char smem[];
    const uint32_t smb = smem_u32(smem);
    const int tid = threadIdx.x;
    const int wid = tid >> 5;
    const int lane = tid & 31;
    const int b   = blockIdx.x >> 5;
    const int h   = blockIdx.x & 31;
    const int kvh = h >> 2;
    const int q0  = blockIdx.y << 6;

    const uint32_t a_lrow = (lane & 15);
    const uint32_t a_lkh  = (lane >> 4) << 4;
    const uint32_t b_lrow = (lane & 7) + ((lane >> 4) << 3);
    const uint32_t b_lkh  = ((lane >> 3) & 1) << 4;
    const int wq = (wid & 3) << 4;
    const int wk = (wid >> 2) << 5;

    // Load + RoPE + scale + split Q tile (64 x 128) -> fp16 hi/lo
#pragma unroll
    for (int it = 0; it < 4; it++) {
        int slot = tid + (it << 8);
        int r = slot >> 4;
        int d = (slot & 15) << 2;
        int srow = q0 + r;
        const float* src = Q + ((size_t)(b * S_LEN + srow)) * (HQ_N * HD_N) + h * HD_N + d;
        float4 x1 = *(const float4*)(src);
        float4 x2 = *(const float4*)(src + 64);
        float4 cs = *(const float4*)(cosb + srow * HD_N + 64 + d);
        float4 sn = *(const float4*)(sinb + srow * HD_N + 64 + d);
        float o1[4] = { (x1.x * cs.x - x2.x * sn.x) * ATTN_SCALE,
                        (x1.y * cs.y - x2.y * sn.y) * ATTN_SCALE,
                        (x1.z * cs.z - x2.z * sn.z) * ATTN_SCALE,
                        (x1.w * cs.w - x2.w * sn.w) * ATTN_SCALE };
        float o2[4] = { (x2.x * cs.x + x1.x * sn.x) * ATTN_SCALE,
                        (x2.y * cs.y + x1.y * sn.y) * ATTN_SCALE,
                        (x2.z * cs.z + x1.z * sn.z) * ATTN_SCALE,
                        (x2.w * cs.w + x1.w * sn.w) * ATTN_SCALE };
        __half* qh = (__half*)(smem + SM_QH) + r * QKV_RS;
        __half* ql = (__half*)(smem + SM_QL) + r * QKV_RS;
#pragma unroll
        for (int u = 0; u < 4; u++) {
            split1h(o1[u], qh[d + u], ql[d + u]);
            split1h(o2[u], qh[d + 64 + u], ql[d + 64 + u]);
        }
    }

    float oacc[4][2][4];
#pragma unroll
    for (int i = 0; i < 4; i++)
#pragma unroll
        for (int j = 0; j < 2; j++)
#pragma unroll
            for (int t = 0; t < 4; t++) oacc[i][j][t] = 0.f;
    float rs0 = 0.f, rs1 = 0.f;

    const __half* kvsrc[2] = { Kf, Vf };
    const uint32_t kvdst[2] = { SM_KF, SM_VF };

    for (int kt = 0; kt < S_LEN; kt += 64) {
        __syncthreads();

        // Copy fp16 K/V chunk (2 arrays)
#pragma unroll
        for (int arr = 0; arr < 2; arr++) {
            const __half* src = kvsrc[arr]
                + ((size_t)(b * S_LEN + kt)) * (HKV_N * HD_N) + kvh * HD_N;
            char* dst = smem + kvdst[arr];
#pragma unroll
            for (int it = 0; it < 4; it++) {
                int slot = tid + (it << 8);
                int r = slot >> 4;
                int cs = slot & 15;
                *(uint4*)(dst + r * (QKV_RS * 2) + (cs << 4)) =
                    *(const uint4*)(src + (size_t)r * (HKV_N * HD_N) + (cs << 3));
            }
        }
        __syncthreads();

        // --- QK^T: Q split-2 x K single ---
        float sacc[4][4];
#pragma unroll
        for (int i = 0; i < 4; i++)
#pragma unroll
            for (int t = 0; t < 4; t++) sacc[i][t] = 0.f;

#pragma unroll
        for (int ks = 0; ks < 8; ks++) {
            const uint32_t ko = ks << 5;
            uint32_t ah[4], al[4];
            {
                uint32_t rowb = (wq + a_lrow) * (QKV_RS * 2) + ko + a_lkh;
                ldm_x4(ah, smb + SM_QH + rowb);
                ldm_x4(al, smb + SM_QL + rowb);
            }
            uint32_t bk[2][4];
#pragma unroll
            for (int g = 0; g < 2; g++) {
                uint32_t rowb = (wk + (g << 4) + b_lrow) * (QKV_RS * 2) + ko + b_lkh;
                ldm_x4(bk[g], smb + SM_KF + rowb);
            }
#pragma unroll
            for (int g = 0; g < 2; g++)
#pragma unroll
                for (int sub = 0; sub < 2; sub++) {
                    int nidx = (g << 1) + sub;
                    const uint32_t* kk = &bk[g][sub << 1];
                    mma_f16(sacc[nidx], ah, kk[0], kk[1]);
                    mma_f16(sacc[nidx], al, kk[0], kk[1]);
                }
        }

        // --- exp, row-sum partials, split-2 P to smem (fp16) ---
        float ps0 = 0.f, ps1 = 0.f;
        const int prow0 = wq + (lane >> 2);
#pragma unroll
        for (int f = 0; f < 4; f++) {
            float p0 = __expf(sacc[f][0]);
            float p1 = __expf(sacc[f][1]);
            float p2 = __expf(sacc[f][2]);
            float p3 = __expf(sacc[f][3]);
            ps0 += p0 + p1;
            ps1 += p2 + p3;
            int col = wk + (f << 3) + ((lane & 3) << 1);
            __half h0, l0, h1, l1;
            split1h(p0, h0, l0); split1h(p1, h1, l1);
            *(__half2*)((__half*)(smem + SM_PH) + prow0 * P_RS + col) = __half2(h0, h1);
            *(__half2*)((__half*)(smem + SM_PL) + prow0 * P_RS + col) = __half2(l0, l1);
            split1h(p2, h0, l0); split1h(p3, h1, l1);
            *(__half2*)((__half*)(smem + SM_PH) + (prow0 + 8) * P_RS + col) = __half2(h0, h1);
            *(__half2*)((__half*)(smem + SM_PL) + (prow0 + 8) * P_RS + col) = __half2(l0, l1);
        }
        ps0 += __shfl_xor_sync(0xFFFFFFFF, ps0, 1);
        ps0 += __shfl_xor_sync(0xFFFFFFFF, ps0, 2);
        ps1 += __shfl_xor_sync(0xFFFFFFFF, ps1, 1);
        ps1 += __shfl_xor_sync(0xFFFFFFFF, ps1, 2);
        rs0 += ps0;
        rs1 += ps1;
        __syncthreads();

        // --- PV: P split-2 x V single ---
        const int nb = wid << 4;
#pragma unroll
        for (int ks = 0; ks < 4; ks++) {
            uint32_t vbf[4];
            {
                uint32_t rowb = ((ks << 4) + (lane & 15)) * (QKV_RS * 2) + ((nb + ((lane >> 4) << 3)) << 1);
                ldm_x4_t(vbf, smb + SM_VF + rowb);
            }
#pragma unroll
            for (int mt = 0; mt < 4; mt++) {
                uint32_t pah[4], pal[4];
                uint32_t rowb = ((mt << 4) + a_lrow) * (P_RS * 2) + (ks << 5) + a_lkh;
                ldm_x4(pah, smb + SM_PH + rowb);
                ldm_x4(pal, smb + SM_PL + rowb);
#pragma unroll
                for (int sub = 0; sub < 2; sub++) {
                    const uint32_t* vv = &vbf[sub << 1];
                    mma_f16(oacc[mt][sub], pah, vv[0], vv[1]);
                    mma_f16(oacc[mt][sub], pal, vv[0], vv[1]);
                }
            }
        }
    }

    float* rssm = (float*)(smem + SM_RS);
    if ((lane & 3) == 0) {
        rssm[((wid >> 2) << 6) + wq + (lane >> 2)] = rs0;
        rssm[((wid >> 2) << 6) + wq + (lane >> 2) + 8] = rs1;
    }
    __syncthreads();

#pragma unroll
    for (int mt = 0; mt < 4; mt++) {
        int r0 = (mt << 4) + (lane >> 2);
        int r1 = r0 + 8;
        float inv0 = 1.0f / (rssm[r0] + rssm[64 + r0]);
        float inv1 = 1.0f / (rssm[r1] + rssm[64 + r1]);
#pragma unroll
        for (int sub = 0; sub < 2; sub++) {
            int col = (wid << 4) + (sub << 3) + ((lane & 3) << 1);
            float v00 = oacc[mt][sub][0] * inv0;
            float v01 = oacc[mt][sub][1] * inv0;
            float v10 = oacc[mt][sub][2] * inv1;
            float v11 = oacc[mt][sub][3] * inv1;
            size_t base0 = ((size_t)(b * S_LEN + q0 + r0)) * D_MODEL + h * HD_N + col;
            size_t base1 = ((size_t)(b * S_LEN + q0 + r1)) * D_MODEL + h * HD_N + col;
            __half h0, l0, h1, l1;
            split1h(v00, h0, l0); split1h(v01, h1, l1);
            *(__half2*)(Oh + base0) = __half2(h0, h1);
            *(__half2*)(Ol + base0) = __half2(l0, l1);
            split1h(v10, h0, l0); split1h(v11, h1, l1);
            *(__half2*)(Oh + base1) = __half2(h0, h1);
            *(__half2*)(Ol + base1) = __half2(l0, l1);
        }
    }
}

// ---------------------------------------------------------------------------
// Launch
// ---------------------------------------------------------------------------
extern "C" void kernel_launch(void* const* d_in, const int* in_sizes, int n_in,
                              void* d_out, int out_size) {
    const float* hidden = (const float*)d_in[0];
    const float* cosb   = (const float*)d_in[1];
    const float* sinb   = (const float*)d_in[2];
    const float* Wq     = (const float*)d_in[3];
    const float* Wk     = (const float*)d_in[4];
    const float* Wv     = (const float*)d_in[5];
    const float* Wo     = (const float*)d_in[6];
    float* out = (float*)d_out;

    float *pQ, *pK, *pV;
    cudaGetSymbolAddress((void**)&pQ, g_Q);
    cudaGetSymbolAddress((void**)&pK, g_K);
    cudaGetSymbolAddress((void**)&pV, g_V);

    __half *hh, *hl, *wq, *wk, *wv, *wo, *ah, *al, *pkf, *pvf;
    cudaGetSymbolAddress((void**)&hh, g_h_hi); cudaGetSymbolAddress((void**)&hl, g_h_lo);
    cudaGetSymbolAddress((void**)&wq, g_wq);   cudaGetSymbolAddress((void**)&wk, g_wk);
    cudaGetSymbolAddress((void**)&wv, g_wv);   cudaGetSymbolAddress((void**)&wo, g_wo);
    cudaGetSymbolAddress((void**)&ah, g_a_hi); cudaGetSymbolAddress((void**)&al, g_a_lo);
    cudaGetSymbolAddress((void**)&pkf, g_kf);  cudaGetSymbolAddress((void**)&pvf, g_vf);

    const int n_big   = 4096 * 4096 / 4;
    const int n_small = 1024 * 4096 / 4;
    split_f16<<<(n_big + 255) / 256, 256>>>(hidden, hh, hl, n_big);
    conv_f16<<<(n_big + 255) / 256, 256>>>(Wq, wq, n_big);
    conv_f16<<<(n_small + 255) / 256, 256>>>(Wk, wk, n_small);
    conv_f16<<<(n_small + 255) / 256, 256>>>(Wv, wv, n_small);
    conv_f16<<<(n_big + 255) / 256, 256>>>(Wo, wo, n_big);

    cudaFuncSetAttribute(gemm_f16x2, cudaFuncAttributeMaxDynamicSharedMemorySize, SM_GEMM);
    gemm_f16x2<<<dim3(32, 32), 256, SM_GEMM>>>(hh, hl, wq, pQ, 4096);
    gemm_f16x2<<<dim3(8, 32),  256, SM_GEMM>>>(hh, hl, wk, pK, 1024);
    gemm_f16x2<<<dim3(8, 32),  256, SM_GEMM>>>(hh, hl, wv, pV, 1024);

    {
        int tot = MROWS * HKV_N * 64;
        kv_prep<<<(tot + 255) / 256, 256>>>(pK, pV, cosb, sinb, pkf, pvf);
    }

    cudaFuncSetAttribute(attn_tc, cudaFuncAttributeMaxDynamicSharedMemorySize, SM_ATTN);
    attn_tc<<<dim3(B_N * HQ_N, S_LEN / 64), 256, SM_ATTN>>>(
        pQ, pkf, pvf, cosb, sinb, ah, al);

    gemm_f16x2<<<dim3(32, 32), 256, SM_GEMM>>>(ah, al, wo, out, 4096);
}

// round 12
// speedup vs baseline: 2.5923x; 1.5660x over previous
#include <cuda_runtime.h>
#include <cuda_bf16.h>
#include <cuda_fp16.h>
#include <math.h>
#include <cstdint>

#define S_LEN   1024
#define B_N     4
#define D_MODEL 4096
#define HQ_N    32
#define HKV_N   8
#define HD_N    128
#define MROWS   4096
#define KDIM    4096
#define ATTN_SCALE 0.08838834764831845f

typedef unsigned long long u64;

__device__ __forceinline__ uint32_t smem_u32(const void* p) {
    uint32_t a;
    asm("{ .reg .u64 t; cvta.to.shared.u64 t, %1; cvt.u32.u64 %0, t; }" : "=r"(a) : "l"(p));
    return a;
}
__device__ __forceinline__ void mma_f16(float (&d)[4], const uint32_t (&a)[4],
                                        const uint32_t b0, const uint32_t b1) {
    asm volatile(
        "mma.sync.aligned.m16n8k16.row.col.f32.f16.f16.f32 "
        "{%0,%1,%2,%3}, {%4,%5,%6,%7}, {%8,%9}, {%0,%1,%2,%3};"
        : "+f"(d[0]), "+f"(d[1]), "+f"(d[2]), "+f"(d[3])
        : "r"(a[0]), "r"(a[1]), "r"(a[2]), "r"(a[3]), "r"(b0), "r"(b1));
}
__device__ __forceinline__ void ldm_x4(uint32_t (&r)[4], uint32_t addr) {
    asm volatile("ldmatrix.sync.aligned.m8n8.x4.shared.b16 {%0,%1,%2,%3}, [%4];"
                 : "=r"(r[0]), "=r"(r[1]), "=r"(r[2]), "=r"(r[3]) : "r"(addr));
}
__device__ __forceinline__ void ldm_x4_t(uint32_t (&r)[4], uint32_t addr) {
    asm volatile("ldmatrix.sync.aligned.m8n8.x4.trans.shared.b16 {%0,%1,%2,%3}, [%4];"
                 : "=r"(r[0]), "=r"(r[1]), "=r"(r[2]), "=r"(r[3]) : "r"(addr));
}
__device__ __forceinline__ void split1h(float x, __half& h, __half& l) {
    h = __float2half_rn(x);
    l = __float2half_rn(x - __half2float(h));
}

// ---------------------------------------------------------------------------
// Scratch
// ---------------------------------------------------------------------------
__device__ float g_Q[(size_t)MROWS * (HQ_N * HD_N)];
__device__ float g_K[(size_t)MROWS * (HKV_N * HD_N)];
__device__ float g_V[(size_t)MROWS * (HKV_N * HD_N)];

__device__ __half g_hid[(size_t)MROWS * D_MODEL];
__device__ __half g_wq[(size_t)4096 * 4096];
__device__ __half g_wk[(size_t)1024 * 4096];
__device__ __half g_wv[(size_t)1024 * 4096];
__device__ __half g_wo[(size_t)4096 * 4096];
__device__ __half g_att[(size_t)MROWS * D_MODEL];
// single fp16 roped K and fp16 V for attention
__device__ __half g_kf[(size_t)MROWS * (HKV_N * HD_N)];
__device__ __half g_vf[(size_t)MROWS * (HKV_N * HD_N)];

// ---------------------------------------------------------------------------
// fp32 -> fp16 single
// ---------------------------------------------------------------------------
__global__ void conv_f16(const float* __restrict__ X,
                         __half* __restrict__ H, int n4) {
    int i = blockIdx.x * blockDim.x + threadIdx.x;
    if (i >= n4) return;
    float4 x = *(const float4*)(X + (size_t)i * 4);
    __half2* Hp = (__half2*)(H + (size_t)i * 4);
    Hp[0] = __half2(__float2half_rn(x.x), __float2half_rn(x.y));
    Hp[1] = __half2(__float2half_rn(x.z), __float2half_rn(x.w));
}

// ---------------------------------------------------------------------------
// K/V prep: RoPE K -> fp16 single, V -> fp16 single
// ---------------------------------------------------------------------------
__global__ void kv_prep(const float* __restrict__ K, const float* __restrict__ V,
                        const float* __restrict__ cosb, const float* __restrict__ sinb,
                        __half* __restrict__ Kf, __half* __restrict__ Vf) {
    int idx = blockIdx.x * blockDim.x + threadIdx.x;
    if (idx >= MROWS * HKV_N * 64) return;
    int d = idx & 63;
    int h = (idx >> 6) & 7;
    int bs = idx >> 9;
    int s = bs & (S_LEN - 1);
    float c  = cosb[s * HD_N + 64 + d];
    float sn = sinb[s * HD_N + 64 + d];
    size_t base = (size_t)bs * (HKV_N * HD_N) + h * HD_N + d;
    float x1 = K[base], x2 = K[base + 64];
    Kf[base]      = __float2half_rn(x1 * c - x2 * sn);
    Kf[base + 64] = __float2half_rn(x2 * c + x1 * sn);
    Vf[base]      = __float2half_rn(V[base]);
    Vf[base + 64] = __float2half_rn(V[base + 64]);
}

// ---------------------------------------------------------------------------
// fp16 single-product GEMM: C = A[M][K] * B[N][K]^T
// register-staged double buffer, BK=64, 2 SMEM arrays (A,B)
// ---------------------------------------------------------------------------
#define SROW   144
#define ATILE  (128 * SROW)        // 18432
#define STAGE  (2 * ATILE)         // 36864
#define SM_GEMM (2 * STAGE)        // 73728
#define NCHUNK (KDIM / 64)

__global__ void __launch_bounds__(256, 1) gemm_f16(
    const __half* __restrict__ A, const __half* __restrict__ B,
    float* __restrict__ C, int Nn) {
    extern __shared__ char smem[];
    const uint32_t smb = smem_u32(smem);
    const int tid = threadIdx.x;
    const int wid = tid >> 5;
    const int lane = tid & 31;
    const int wm = (wid >> 2) << 6;
    const int wn = (wid & 3) << 5;
    const int n0 = blockIdx.x << 7;
    const int m0 = blockIdx.y << 7;

    const __half* srcs[2] = { A + (size_t)m0 * KDIM, B + (size_t)n0 * KDIM };

    int r_ld[4], sseg[4];
#pragma unroll
    for (int i = 0; i < 4; i++) {
        int slot = tid + (i << 8);
        r_ld[i] = slot >> 3;
        sseg[i] = (slot & 7) << 3;
    }

    float acc[4][4][4];
#pragma unroll
    for (int i = 0; i < 4; i++)
#pragma unroll
        for (int j = 0; j < 4; j++)
#pragma unroll
            for (int t = 0; t < 4; t++) acc[i][j][t] = 0.f;

    // prologue: chunk 0 -> stage 0
#pragma unroll
    for (int arr = 0; arr < 2; arr++) {
        char* dst = smem + arr * ATILE;
        const __half* src = srcs[arr];
#pragma unroll
        for (int i = 0; i < 4; i++)
            *(uint4*)(dst + r_ld[i] * SROW + (sseg[i] << 1)) =
                *(const uint4*)(src + (size_t)r_ld[i] * KDIM + sseg[i]);
    }
    __syncthreads();

    const uint32_t a_lrow = (lane & 15);
    const uint32_t a_lkh  = (lane >> 4) << 4;
    const uint32_t b_lrow = (lane & 7) + ((lane >> 4) << 3);
    const uint32_t b_lkh  = ((lane >> 3) & 1) << 4;

    uint4 regs[8];

    for (int c = 0; c < NCHUNK; c++) {
        const int s = c & 1;
        const uint32_t sb = smb + s * STAGE;
        const bool more = (c + 1 < NCHUNK);
        if (more) {
            const int k0 = (c + 1) << 6;
#pragma unroll
            for (int arr = 0; arr < 2; arr++)
#pragma unroll
                for (int i = 0; i < 4; i++)
                    regs[arr * 4 + i] =
                        *(const uint4*)(srcs[arr] + (size_t)r_ld[i] * KDIM + k0 + sseg[i]);
        }

#pragma unroll
        for (int ks = 0; ks < 4; ks++) {
            const uint32_t ko = ks << 5;
            uint32_t af[4][4];
#pragma unroll
            for (int i = 0; i < 4; i++) {
                uint32_t rowb = (wm + (i << 4) + a_lrow) * SROW + ko + a_lkh;
                ldm_x4(af[i], sb + 0 * ATILE + rowb);
            }
            uint32_t bf[2][4];
#pragma unroll
            for (int j2 = 0; j2 < 2; j2++) {
                uint32_t rowb = (wn + (j2 << 4) + b_lrow) * SROW + ko + b_lkh;
                ldm_x4(bf[j2], sb + 1 * ATILE + rowb);
            }
#pragma unroll
            for (int i = 0; i < 4; i++)
#pragma unroll
                for (int j = 0; j < 4; j++) {
                    const uint32_t* bb = &bf[j >> 1][(j & 1) << 1];
                    mma_f16(acc[i][j], af[i], bb[0], bb[1]);
                }
        }

        if (more) {
            const int so = (s ^ 1) * STAGE;
#pragma unroll
            for (int arr = 0; arr < 2; arr++)
#pragma unroll
                for (int i = 0; i < 4; i++)
                    *(uint4*)(smem + so + arr * ATILE + r_ld[i] * SROW + (sseg[i] << 1)) =
                        regs[arr * 4 + i];
        }
        __syncthreads();
    }

    const int erow = m0 + wm + (lane >> 2);
    const int ecol = n0 + wn + ((lane & 3) << 1);
#pragma unroll
    for (int i = 0; i < 4; i++) {
#pragma unroll
        for (int j = 0; j < 4; j++) {
            float* p0 = C + (size_t)(erow + (i << 4)) * Nn + ecol + (j << 3);
            float* p1 = p0 + (size_t)8 * Nn;
            *(float2*)p0 = make_float2(acc[i][j][0], acc[i][j][1]);
            *(float2*)p1 = make_float2(acc[i][j][2], acc[i][j][3]);
        }
    }
}

// ---------------------------------------------------------------------------
// Tensor-core attention (R11 numerics; output single fp16 only)
// ---------------------------------------------------------------------------
#define QKV_RS 136
#define P_RS   72
#define SM_QH  0
#define SM_QL  17408
#define SM_KF  34816
#define SM_VF  52224
#define SM_PH  69632
#define SM_PL  78848
#define SM_RS  88064
#define SM_ATTN (SM_RS + 512)

__global__ void __launch_bounds__(256, 1) attn_tc(
    const float* __restrict__ Q,
    const __half* __restrict__ Kf, const __half* __restrict__ Vf,
    const float* __restrict__ cosb, const float* __restrict__ sinb,
    __half* __restrict__ Oh) {
    extern __shared__ char smem[];
    const uint32_t smb = smem_u32(smem);
    const int tid = threadIdx.x;
    const int wid = tid >> 5;
    const int lane = tid & 31;
    const int b   = blockIdx.x >> 5;
    const int h   = blockIdx.x & 31;
    const int kvh = h >> 2;
    const int q0  = blockIdx.y << 6;

    const uint32_t a_lrow = (lane & 15);
    const uint32_t a_lkh  = (lane >> 4) << 4;
    const uint32_t b_lrow = (lane & 7) + ((lane >> 4) << 3);
    const uint32_t b_lkh  = ((lane >> 3) & 1) << 4;
    const int wq = (wid & 3) << 4;
    const int wk = (wid >> 2) << 5;

    // Load + RoPE + scale + split-2 Q tile -> fp16 hi/lo
#pragma unroll
    for (int it = 0; it < 4; it++) {
        int slot = tid + (it << 8);
        int r = slot >> 4;
        int d = (slot & 15) << 2;
        int srow = q0 + r;
        const float* src = Q + ((size_t)(b * S_LEN + srow)) * (HQ_N * HD_N) + h * HD_N + d;
        float4 x1 = *(const float4*)(src);
        float4 x2 = *(const float4*)(src + 64);
        float4 cs = *(const float4*)(cosb + srow * HD_N + 64 + d);
        float4 sn = *(const float4*)(sinb + srow * HD_N + 64 + d);
        float o1[4] = { (x1.x * cs.x - x2.x * sn.x) * ATTN_SCALE,
                        (x1.y * cs.y - x2.y * sn.y) * ATTN_SCALE,
                        (x1.z * cs.z - x2.z * sn.z) * ATTN_SCALE,
                        (x1.w * cs.w - x2.w * sn.w) * ATTN_SCALE };
        float o2[4] = { (x2.x * cs.x + x1.x * sn.x) * ATTN_SCALE,
                        (x2.y * cs.y + x1.y * sn.y) * ATTN_SCALE,
                        (x2.z * cs.z + x1.z * sn.z) * ATTN_SCALE,
                        (x2.w * cs.w + x1.w * sn.w) * ATTN_SCALE };
        __half* qh = (__half*)(smem + SM_QH) + r * QKV_RS;
        __half* ql = (__half*)(smem + SM_QL) + r * QKV_RS;
#pragma unroll
        for (int u = 0; u < 4; u++) {
            split1h(o1[u], qh[d + u], ql[d + u]);
            split1h(o2[u], qh[d + 64 + u], ql[d + 64 + u]);
        }
    }

    float oacc[4][2][4];
#pragma unroll
    for (int i = 0; i < 4; i++)
#pragma unroll
        for (int j = 0; j < 2; j++)
#pragma unroll
            for (int t = 0; t < 4; t++) oacc[i][j][t] = 0.f;
    float rs0 = 0.f, rs1 = 0.f;

    const __half* kvsrc[2] = { Kf, Vf };
    const uint32_t kvdst[2] = { SM_KF, SM_VF };

    for (int kt = 0; kt < S_LEN; kt += 64) {
        __syncthreads();

#pragma unroll
        for (int arr = 0; arr < 2; arr++) {
            const __half* src = kvsrc[arr]
                + ((size_t)(b * S_LEN + kt)) * (HKV_N * HD_N) + kvh * HD_N;
            char* dst = smem + kvdst[arr];
#pragma unroll
            for (int it = 0; it < 4; it++) {
                int slot = tid + (it << 8);
                int r = slot >> 4;
                int cs = slot & 15;
                *(uint4*)(dst + r * (QKV_RS * 2) + (cs << 4)) =
                    *(const uint4*)(src + (size_t)r * (HKV_N * HD_N) + (cs << 3));
            }
        }
        __syncthreads();

        // QK^T: Q split-2 x K single
        float sacc[4][4];
#pragma unroll
        for (int i = 0; i < 4; i++)
#pragma unroll
            for (int t = 0; t < 4; t++) sacc[i][t] = 0.f;

#pragma unroll
        for (int ks = 0; ks < 8; ks++) {
            const uint32_t ko = ks << 5;
            uint32_t ah[4], al[4];
            {
                uint32_t rowb = (wq + a_lrow) * (QKV_RS * 2) + ko + a_lkh;
                ldm_x4(ah, smb + SM_QH + rowb);
                ldm_x4(al, smb + SM_QL + rowb);
            }
            uint32_t bk[2][4];
#pragma unroll
            for (int g = 0; g < 2; g++) {
                uint32_t rowb = (wk + (g << 4) + b_lrow) * (QKV_RS * 2) + ko + b_lkh;
                ldm_x4(bk[g], smb + SM_KF + rowb);
            }
#pragma unroll
            for (int g = 0; g < 2; g++)
#pragma unroll
                for (int sub = 0; sub < 2; sub++) {
                    int nidx = (g << 1) + sub;
                    const uint32_t* kk = &bk[g][sub << 1];
                    mma_f16(sacc[nidx], ah, kk[0], kk[1]);
                    mma_f16(sacc[nidx], al, kk[0], kk[1]);
                }
        }

        // exp, row-sum partials, split-2 P
        float ps0 = 0.f, ps1 = 0.f;
        const int prow0 = wq + (lane >> 2);
#pragma unroll
        for (int f = 0; f < 4; f++) {
            float p0 = __expf(sacc[f][0]);
            float p1 = __expf(sacc[f][1]);
            float p2 = __expf(sacc[f][2]);
            float p3 = __expf(sacc[f][3]);
            ps0 += p0 + p1;
            ps1 += p2 + p3;
            int col = wk + (f << 3) + ((lane & 3) << 1);
            __half h0, l0, h1, l1;
            split1h(p0, h0, l0); split1h(p1, h1, l1);
            *(__half2*)((__half*)(smem + SM_PH) + prow0 * P_RS + col) = __half2(h0, h1);
            *(__half2*)((__half*)(smem + SM_PL) + prow0 * P_RS + col) = __half2(l0, l1);
            split1h(p2, h0, l0); split1h(p3, h1, l1);
            *(__half2*)((__half*)(smem + SM_PH) + (prow0 + 8) * P_RS + col) = __half2(h0, h1);
            *(__half2*)((__half*)(smem + SM_PL) + (prow0 + 8) * P_RS + col) = __half2(l0, l1);
        }
        ps0 += __shfl_xor_sync(0xFFFFFFFF, ps0, 1);
        ps0 += __shfl_xor_sync(0xFFFFFFFF, ps0, 2);
        ps1 += __shfl_xor_sync(0xFFFFFFFF, ps1, 1);
        ps1 += __shfl_xor_sync(0xFFFFFFFF, ps1, 2);
        rs0 += ps0;
        rs1 += ps1;
        __syncthreads();

        // PV: P split-2 x V single
        const int nb = wid << 4;
#pragma unroll
        for (int ks = 0; ks < 4; ks++) {
            uint32_t vbf[4];
            {
                uint32_t rowb = ((ks << 4) + (lane & 15)) * (QKV_RS * 2) + ((nb + ((lane >> 4) << 3)) << 1);
                ldm_x4_t(vbf, smb + SM_VF + rowb);
            }
#pragma unroll
            for (int mt = 0; mt < 4; mt++) {
                uint32_t pah[4], pal[4];
                uint32_t rowb = ((mt << 4) + a_lrow) * (P_RS * 2) + (ks << 5) + a_lkh;
                ldm_x4(pah, smb + SM_PH + rowb);
                ldm_x4(pal, smb + SM_PL + rowb);
#pragma unroll
                for (int sub = 0; sub < 2; sub++) {
                    const uint32_t* vv = &vbf[sub << 1];
                    mma_f16(oacc[mt][sub], pah, vv[0], vv[1]);
                    mma_f16(oacc[mt][sub], pal, vv[0], vv[1]);
                }
            }
        }
    }

    float* rssm = (float*)(smem + SM_RS);
    if ((lane & 3) == 0) {
        rssm[((wid >> 2) << 6) + wq + (lane >> 2)] = rs0;
        rssm[((wid >> 2) << 6) + wq + (lane >> 2) + 8] = rs1;
    }
    __syncthreads();

#pragma unroll
    for (int mt = 0; mt < 4; mt++) {
        int r0 = (mt << 4) + (lane >> 2);
        int r1 = r0 + 8;
        float inv0 = 1.0f / (rssm[r0] + rssm[64 + r0]);
        float inv1 = 1.0f / (rssm[r1] + rssm[64 + r1]);
#pragma unroll
        for (int sub = 0; sub < 2; sub++) {
            int col = (wid << 4) + (sub << 3) + ((lane & 3) << 1);
            float v00 = oacc[mt][sub][0] * inv0;
            float v01 = oacc[mt][sub][1] * inv0;
            float v10 = oacc[mt][sub][2] * inv1;
            float v11 = oacc[mt][sub][3] * inv1;
            size_t base0 = ((size_t)(b * S_LEN + q0 + r0)) * D_MODEL + h * HD_N + col;
            size_t base1 = ((size_t)(b * S_LEN + q0 + r1)) * D_MODEL + h * HD_N + col;
            *(__half2*)(Oh + base0) = __half2(__float2half_rn(v00), __float2half_rn(v01));
            *(__half2*)(Oh + base1) = __half2(__float2half_rn(v10), __float2half_rn(v11));
        }
    }
}

// ---------------------------------------------------------------------------
// Launch
// ---------------------------------------------------------------------------
extern "C" void kernel_launch(void* const* d_in, const int* in_sizes, int n_in,
                              void* d_out, int out_size) {
    const float* hidden = (const float*)d_in[0];
    const float* cosb   = (const float*)d_in[1];
    const float* sinb   = (const float*)d_in[2];
    const float* Wq     = (const float*)d_in[3];
    const float* Wk     = (const float*)d_in[4];
    const float* Wv     = (const float*)d_in[5];
    const float* Wo     = (const float*)d_in[6];
    float* out = (float*)d_out;

    float *pQ, *pK, *pV;
    cudaGetSymbolAddress((void**)&pQ, g_Q);
    cudaGetSymbolAddress((void**)&pK, g_K);
    cudaGetSymbolAddress((void**)&pV, g_V);

    __half *hid, *wq, *wk, *wv, *wo, *att, *pkf, *pvf;
    cudaGetSymbolAddress((void**)&hid, g_hid);
    cudaGetSymbolAddress((void**)&wq, g_wq);   cudaGetSymbolAddress((void**)&wk, g_wk);
    cudaGetSymbolAddress((void**)&wv, g_wv);   cudaGetSymbolAddress((void**)&wo, g_wo);
    cudaGetSymbolAddress((void**)&att, g_att);
    cudaGetSymbolAddress((void**)&pkf, g_kf);  cudaGetSymbolAddress((void**)&pvf, g_vf);

    const int n_big   = 4096 * 4096 / 4;
    const int n_small = 1024 * 4096 / 4;
    conv_f16<<<(n_big + 255) / 256, 256>>>(hidden, hid, n_big);
    conv_f16<<<(n_big + 255) / 256, 256>>>(Wq, wq, n_big);
    conv_f16<<<(n_small + 255) / 256, 256>>>(Wk, wk, n_small);
    conv_f16<<<(n_small + 255) / 256, 256>>>(Wv, wv, n_small);
    conv_f16<<<(n_big + 255) / 256, 256>>>(Wo, wo, n_big);

    cudaFuncSetAttribute(gemm_f16, cudaFuncAttributeMaxDynamicSharedMemorySize, SM_GEMM);
    gemm_f16<<<dim3(32, 32), 256, SM_GEMM>>>(hid, wq, pQ, 4096);
    gemm_f16<<<dim3(8, 32),  256, SM_GEMM>>>(hid, wk, pK, 1024);
    gemm_f16<<<dim3(8, 32),  256, SM_GEMM>>>(hid, wv, pV, 1024);

    {
        int tot = MROWS * HKV_N * 64;
        kv_prep<<<(tot + 255) / 256, 256>>>(pK, pV, cosb, sinb, pkf, pvf);
    }

    cudaFuncSetAttribute(attn_tc, cudaFuncAttributeMaxDynamicSharedMemorySize, SM_ATTN);
    attn_tc<<<dim3(B_N * HQ_N, S_LEN / 64), 256, SM_ATTN>>>(
        pQ, pkf, pvf, cosb, sinb, att);

    gemm_f16<<<dim3(32, 32), 256, SM_GEMM>>>(att, wo, out, 4096);
}

// round 13
// speedup vs baseline: 2.6462x; 1.0208x over previous
#include <cuda_runtime.h>
#include <cuda_bf16.h>
#include <cuda_fp16.h>
#include <math.h>
#include <cstdint>

#define S_LEN   1024
#define B_N     4
#define D_MODEL 4096
#define HQ_N    32
#define HKV_N   8
#define HD_N    128
#define MROWS   4096
#define KDIM    4096
#define ATTN_SCALE 0.08838834764831845f

typedef unsigned long long u64;

__device__ __forceinline__ uint32_t smem_u32(const void* p) {
    uint32_t a;
    asm("{ .reg .u64 t; cvta.to.shared.u64 t, %1; cvt.u32.u64 %0, t; }" : "=r"(a) : "l"(p));
    return a;
}
__device__ __forceinline__ void mma_f16(float (&d)[4], const uint32_t (&a)[4],
                                        const uint32_t b0, const uint32_t b1) {
    asm volatile(
        "mma.sync.aligned.m16n8k16.row.col.f32.f16.f16.f32 "
        "{%0,%1,%2,%3}, {%4,%5,%6,%7}, {%8,%9}, {%0,%1,%2,%3};"
        : "+f"(d[0]), "+f"(d[1]), "+f"(d[2]), "+f"(d[3])
        : "r"(a[0]), "r"(a[1]), "r"(a[2]), "r"(a[3]), "r"(b0), "r"(b1));
}
__device__ __forceinline__ void ldm_x4(uint32_t (&r)[4], uint32_t addr) {
    asm volatile("ldmatrix.sync.aligned.m8n8.x4.shared.b16 {%0,%1,%2,%3}, [%4];"
                 : "=r"(r[0]), "=r"(r[1]), "=r"(r[2]), "=r"(r[3]) : "r"(addr));
}
__device__ __forceinline__ void ldm_x4_t(uint32_t (&r)[4], uint32_t addr) {
    asm volatile("ldmatrix.sync.aligned.m8n8.x4.trans.shared.b16 {%0,%1,%2,%3}, [%4];"
                 : "=r"(r[0]), "=r"(r[1]), "=r"(r[2]), "=r"(r[3]) : "r"(addr));
}

// ---------------------------------------------------------------------------
// Scratch
// ---------------------------------------------------------------------------
__device__ float g_Q[(size_t)MROWS * (HQ_N * HD_N)];
__device__ float g_K[(size_t)MROWS * (HKV_N * HD_N)];
__device__ float g_V[(size_t)MROWS * (HKV_N * HD_N)];

__device__ __half g_hid[(size_t)MROWS * D_MODEL];
__device__ __half g_wq[(size_t)4096 * 4096];
__device__ __half g_wk[(size_t)1024 * 4096];
__device__ __half g_wv[(size_t)1024 * 4096];
__device__ __half g_wo[(size_t)4096 * 4096];
__device__ __half g_att[(size_t)MROWS * D_MODEL];
__device__ __half g_kf[(size_t)MROWS * (HKV_N * HD_N)];
__device__ __half g_vf[(size_t)MROWS * (HKV_N * HD_N)];

// ---------------------------------------------------------------------------
// fp32 -> fp16 single
// ---------------------------------------------------------------------------
__global__ void conv_f16(const float* __restrict__ X,
                         __half* __restrict__ H, int n4) {
    int i = blockIdx.x * blockDim.x + threadIdx.x;
    if (i >= n4) return;
    float4 x = *(const float4*)(X + (size_t)i * 4);
    __half2* Hp = (__half2*)(H + (size_t)i * 4);
    Hp[0] = __half2(__float2half_rn(x.x), __float2half_rn(x.y));
    Hp[1] = __half2(__float2half_rn(x.z), __float2half_rn(x.w));
}

// ---------------------------------------------------------------------------
// K/V prep: RoPE K -> fp16, V -> fp16
// ---------------------------------------------------------------------------
__global__ void kv_prep(const float* __restrict__ K, const float* __restrict__ V,
                        const float* __restrict__ cosb, const float* __restrict__ sinb,
                        __half* __restrict__ Kf, __half* __restrict__ Vf) {
    int idx = blockIdx.x * blockDim.x + threadIdx.x;
    if (idx >= MROWS * HKV_N * 64) return;
    int d = idx & 63;
    int h = (idx >> 6) & 7;
    int bs = idx >> 9;
    int s = bs & (S_LEN - 1);
    float c  = cosb[s * HD_N + 64 + d];
    float sn = sinb[s * HD_N + 64 + d];
    size_t base = (size_t)bs * (HKV_N * HD_N) + h * HD_N + d;
    float x1 = K[base], x2 = K[base + 64];
    Kf[base]      = __float2half_rn(x1 * c - x2 * sn);
    Kf[base + 64] = __float2half_rn(x2 * c + x1 * sn);
    Vf[base]      = __float2half_rn(V[base]);
    Vf[base + 64] = __float2half_rn(V[base + 64]);
}

// ---------------------------------------------------------------------------
// fp16 single-product GEMM (unchanged from R12)
// ---------------------------------------------------------------------------
#define SROW   144
#define ATILE  (128 * SROW)
#define STAGE  (2 * ATILE)
#define SM_GEMM (2 * STAGE)
#define NCHUNK (KDIM / 64)

__global__ void __launch_bounds__(256, 1) gemm_f16(
    const __half* __restrict__ A, const __half* __restrict__ B,
    float* __restrict__ C, int Nn) {
    extern __shared__ char smem[];
    const uint32_t smb = smem_u32(smem);
    const int tid = threadIdx.x;
    const int wid = tid >> 5;
    const int lane = tid & 31;
    const int wm = (wid >> 2) << 6;
    const int wn = (wid & 3) << 5;
    const int n0 = blockIdx.x << 7;
    const int m0 = blockIdx.y << 7;

    const __half* srcs[2] = { A + (size_t)m0 * KDIM, B + (size_t)n0 * KDIM };

    int r_ld[4], sseg[4];
#pragma unroll
    for (int i = 0; i < 4; i++) {
        int slot = tid + (i << 8);
        r_ld[i] = slot >> 3;
        sseg[i] = (slot & 7) << 3;
    }

    float acc[4][4][4];
#pragma unroll
    for (int i = 0; i < 4; i++)
#pragma unroll
        for (int j = 0; j < 4; j++)
#pragma unroll
            for (int t = 0; t < 4; t++) acc[i][j][t] = 0.f;

#pragma unroll
    for (int arr = 0; arr < 2; arr++) {
        char* dst = smem + arr * ATILE;
        const __half* src = srcs[arr];
#pragma unroll
        for (int i = 0; i < 4; i++)
            *(uint4*)(dst + r_ld[i] * SROW + (sseg[i] << 1)) =
                *(const uint4*)(src + (size_t)r_ld[i] * KDIM + sseg[i]);
    }
    __syncthreads();

    const uint32_t a_lrow = (lane & 15);
    const uint32_t a_lkh  = (lane >> 4) << 4;
    const uint32_t b_lrow = (lane & 7) + ((lane >> 4) << 3);
    const uint32_t b_lkh  = ((lane >> 3) & 1) << 4;

    uint4 regs[8];

    for (int c = 0; c < NCHUNK; c++) {
        const int s = c & 1;
        const uint32_t sb = smb + s * STAGE;
        const bool more = (c + 1 < NCHUNK);
        if (more) {
            const int k0 = (c + 1) << 6;
#pragma unroll
            for (int arr = 0; arr < 2; arr++)
#pragma unroll
                for (int i = 0; i < 4; i++)
                    regs[arr * 4 + i] =
                        *(const uint4*)(srcs[arr] + (size_t)r_ld[i] * KDIM + k0 + sseg[i]);
        }

#pragma unroll
        for (int ks = 0; ks < 4; ks++) {
            const uint32_t ko = ks << 5;
            uint32_t af[4][4];
#pragma unroll
            for (int i = 0; i < 4; i++) {
                uint32_t rowb = (wm + (i << 4) + a_lrow) * SROW + ko + a_lkh;
                ldm_x4(af[i], sb + 0 * ATILE + rowb);
            }
            uint32_t bf[2][4];
#pragma unroll
            for (int j2 = 0; j2 < 2; j2++) {
                uint32_t rowb = (wn + (j2 << 4) + b_lrow) * SROW + ko + b_lkh;
                ldm_x4(bf[j2], sb + 1 * ATILE + rowb);
            }
#pragma unroll
            for (int i = 0; i < 4; i++)
#pragma unroll
                for (int j = 0; j < 4; j++) {
                    const uint32_t* bb = &bf[j >> 1][(j & 1) << 1];
                    mma_f16(acc[i][j], af[i], bb[0], bb[1]);
                }
        }

        if (more) {
            const int so = (s ^ 1) * STAGE;
#pragma unroll
            for (int arr = 0; arr < 2; arr++)
#pragma unroll
                for (int i = 0; i < 4; i++)
                    *(uint4*)(smem + so + arr * ATILE + r_ld[i] * SROW + (sseg[i] << 1)) =
                        regs[arr * 4 + i];
        }
        __syncthreads();
    }

    const int erow = m0 + wm + (lane >> 2);
    const int ecol = n0 + wn + ((lane & 3) << 1);
#pragma unroll
    for (int i = 0; i < 4; i++) {
#pragma unroll
        for (int j = 0; j < 4; j++) {
            float* p0 = C + (size_t)(erow + (i << 4)) * Nn + ecol + (j << 3);
            float* p1 = p0 + (size_t)8 * Nn;
            *(float2*)p0 = make_float2(acc[i][j][0], acc[i][j][1]);
            *(float2*)p1 = make_float2(acc[i][j][2], acc[i][j][3]);
        }
    }
}

// ---------------------------------------------------------------------------
// Tensor-core attention: all single fp16 (Q x K, P x V — 1 mma per product)
// ---------------------------------------------------------------------------
#define QKV_RS 136
#define P_RS   72
#define SM_QF  0
#define SM_KF  17408
#define SM_VF  34816
#define SM_PF  52224
#define SM_RS  61440
#define SM_ATTN (SM_RS + 512)

__global__ void __launch_bounds__(256, 1) attn_tc(
    const float* __restrict__ Q,
    const __half* __restrict__ Kf, const __half* __restrict__ Vf,
    const float* __restrict__ cosb, const float* __restrict__ sinb,
    __half* __restrict__ Oh) {
    extern __shared__ char smem[];
    const uint32_t smb = smem_u32(smem);
    const int tid = threadIdx.x;
    const int wid = tid >> 5;
    const int lane = tid & 31;
    const int b   = blockIdx.x >> 5;
    const int h   = blockIdx.x & 31;
    const int kvh = h >> 2;
    const int q0  = blockIdx.y << 6;

    const uint32_t a_lrow = (lane & 15);
    const uint32_t a_lkh  = (lane >> 4) << 4;
    const uint32_t b_lrow = (lane & 7) + ((lane >> 4) << 3);
    const uint32_t b_lkh  = ((lane >> 3) & 1) << 4;
    const int wq = (wid & 3) << 4;
    const int wk = (wid >> 2) << 5;

    // Load + RoPE + scale Q tile -> single fp16
#pragma unroll
    for (int it = 0; it < 4; it++) {
        int slot = tid + (it << 8);
        int r = slot >> 4;
        int d = (slot & 15) << 2;
        int srow = q0 + r;
        const float* src = Q + ((size_t)(b * S_LEN + srow)) * (HQ_N * HD_N) + h * HD_N + d;
        float4 x1 = *(const float4*)(src);
        float4 x2 = *(const float4*)(src + 64);
        float4 cs = *(const float4*)(cosb + srow * HD_N + 64 + d);
        float4 sn = *(const float4*)(sinb + srow * HD_N + 64 + d);
        __half* qf = (__half*)(smem + SM_QF) + r * QKV_RS;
        qf[d + 0] = __float2half_rn((x1.x * cs.x - x2.x * sn.x) * ATTN_SCALE);
        qf[d + 1] = __float2half_rn((x1.y * cs.y - x2.y * sn.y) * ATTN_SCALE);
        qf[d + 2] = __float2half_rn((x1.z * cs.z - x2.z * sn.z) * ATTN_SCALE);
        qf[d + 3] = __float2half_rn((x1.w * cs.w - x2.w * sn.w) * ATTN_SCALE);
        qf[d + 64] = __float2half_rn((x2.x * cs.x + x1.x * sn.x) * ATTN_SCALE);
        qf[d + 65] = __float2half_rn((x2.y * cs.y + x1.y * sn.y) * ATTN_SCALE);
        qf[d + 66] = __float2half_rn((x2.z * cs.z + x1.z * sn.z) * ATTN_SCALE);
        qf[d + 67] = __float2half_rn((x2.w * cs.w + x1.w * sn.w) * ATTN_SCALE);
    }

    float oacc[4][2][4];
#pragma unroll
    for (int i = 0; i < 4; i++)
#pragma unroll
        for (int j = 0; j < 2; j++)
#pragma unroll
            for (int t = 0; t < 4; t++) oacc[i][j][t] = 0.f;
    float rs0 = 0.f, rs1 = 0.f;

    const __half* kvsrc[2] = { Kf, Vf };
    const uint32_t kvdst[2] = { SM_KF, SM_VF };

    for (int kt = 0; kt < S_LEN; kt += 64) {
        __syncthreads();

#pragma unroll
        for (int arr = 0; arr < 2; arr++) {
            const __half* src = kvsrc[arr]
                + ((size_t)(b * S_LEN + kt)) * (HKV_N * HD_N) + kvh * HD_N;
            char* dst = smem + kvdst[arr];
#pragma unroll
            for (int it = 0; it < 4; it++) {
                int slot = tid + (it << 8);
                int r = slot >> 4;
                int cs = slot & 15;
                *(uint4*)(dst + r * (QKV_RS * 2) + (cs << 4)) =
                    *(const uint4*)(src + (size_t)r * (HKV_N * HD_N) + (cs << 3));
            }
        }
        __syncthreads();

        // QK^T: single x single
        float sacc[4][4];
#pragma unroll
        for (int i = 0; i < 4; i++)
#pragma unroll
            for (int t = 0; t < 4; t++) sacc[i][t] = 0.f;

#pragma unroll
        for (int ks = 0; ks < 8; ks++) {
            const uint32_t ko = ks << 5;
            uint32_t aq[4];
            {
                uint32_t rowb = (wq + a_lrow) * (QKV_RS * 2) + ko + a_lkh;
                ldm_x4(aq, smb + SM_QF + rowb);
            }
            uint32_t bk[2][4];
#pragma unroll
            for (int g = 0; g < 2; g++) {
                uint32_t rowb = (wk + (g << 4) + b_lrow) * (QKV_RS * 2) + ko + b_lkh;
                ldm_x4(bk[g], smb + SM_KF + rowb);
            }
#pragma unroll
            for (int g = 0; g < 2; g++)
#pragma unroll
                for (int sub = 0; sub < 2; sub++) {
                    int nidx = (g << 1) + sub;
                    const uint32_t* kk = &bk[g][sub << 1];
                    mma_f16(sacc[nidx], aq, kk[0], kk[1]);
                }
        }

        // exp, row-sum partials, single-fp16 P
        float ps0 = 0.f, ps1 = 0.f;
        const int prow0 = wq + (lane >> 2);
#pragma unroll
        for (int f = 0; f < 4; f++) {
            float p0 = __expf(sacc[f][0]);
            float p1 = __expf(sacc[f][1]);
            float p2 = __expf(sacc[f][2]);
            float p3 = __expf(sacc[f][3]);
            ps0 += p0 + p1;
            ps1 += p2 + p3;
            int col = wk + (f << 3) + ((lane & 3) << 1);
            *(__half2*)((__half*)(smem + SM_PF) + prow0 * P_RS + col) =
                __half2(__float2half_rn(p0), __float2half_rn(p1));
            *(__half2*)((__half*)(smem + SM_PF) + (prow0 + 8) * P_RS + col) =
                __half2(__float2half_rn(p2), __float2half_rn(p3));
        }
        ps0 += __shfl_xor_sync(0xFFFFFFFF, ps0, 1);
        ps0 += __shfl_xor_sync(0xFFFFFFFF, ps0, 2);
        ps1 += __shfl_xor_sync(0xFFFFFFFF, ps1, 1);
        ps1 += __shfl_xor_sync(0xFFFFFFFF, ps1, 2);
        rs0 += ps0;
        rs1 += ps1;
        __syncthreads();

        // PV: single x single
        const int nb = wid << 4;
#pragma unroll
        for (int ks = 0; ks < 4; ks++) {
            uint32_t vbf[4];
            {
                uint32_t rowb = ((ks << 4) + (lane & 15)) * (QKV_RS * 2) + ((nb + ((lane >> 4) << 3)) << 1);
                ldm_x4_t(vbf, smb + SM_VF + rowb);
            }
#pragma unroll
            for (int mt = 0; mt < 4; mt++) {
                uint32_t pf[4];
                uint32_t rowb = ((mt << 4) + a_lrow) * (P_RS * 2) + (ks << 5) + a_lkh;
                ldm_x4(pf, smb + SM_PF + rowb);
#pragma unroll
                for (int sub = 0; sub < 2; sub++) {
                    const uint32_t* vv = &vbf[sub << 1];
                    mma_f16(oacc[mt][sub], pf, vv[0], vv[1]);
                }
            }
        }
    }

    float* rssm = (float*)(smem + SM_RS);
    if ((lane & 3) == 0) {
        rssm[((wid >> 2) << 6) + wq + (lane >> 2)] = rs0;
        rssm[((wid >> 2) << 6) + wq + (lane >> 2) + 8] = rs1;
    }
    __syncthreads();

#pragma unroll
    for (int mt = 0; mt < 4; mt++) {
        int r0 = (mt << 4) + (lane >> 2);
        int r1 = r0 + 8;
        float inv0 = 1.0f / (rssm[r0] + rssm[64 + r0]);
        float inv1 = 1.0f / (rssm[r1] + rssm[64 + r1]);
#pragma unroll
        for (int sub = 0; sub < 2; sub++) {
            int col = (wid << 4) + (sub << 3) + ((lane & 3) << 1);
            float v00 = oacc[mt][sub][0] * inv0;
            float v01 = oacc[mt][sub][1] * inv0;
            float v10 = oacc[mt][sub][2] * inv1;
            float v11 = oacc[mt][sub][3] * inv1;
            size_t base0 = ((size_t)(b * S_LEN + q0 + r0)) * D_MODEL + h * HD_N + col;
            size_t base1 = ((size_t)(b * S_LEN + q0 + r1)) * D_MODEL + h * HD_N + col;
            *(__half2*)(Oh + base0) = __half2(__float2half_rn(v00), __float2half_rn(v01));
            *(__half2*)(Oh + base1) = __half2(__float2half_rn(v10), __float2half_rn(v11));
        }
    }
}

// ---------------------------------------------------------------------------
// Launch
// ---------------------------------------------------------------------------
extern "C" void kernel_launch(void* const* d_in, const int* in_sizes, int n_in,
                              void* d_out, int out_size) {
    const float* hidden = (const float*)d_in[0];
    const float* cosb   = (const float*)d_in[1];
    const float* sinb   = (const float*)d_in[2];
    const float* Wq     = (const float*)d_in[3];
    const float* Wk     = (const float*)d_in[4];
    const float* Wv     = (const float*)d_in[5];
    const float* Wo     = (const float*)d_in[6];
    float* out = (float*)d_out;

    float *pQ, *pK, *pV;
    cudaGetSymbolAddress((void**)&pQ, g_Q);
    cudaGetSymbolAddress((void**)&pK, g_K);
    cudaGetSymbolAddress((void**)&pV, g_V);

    __half *hid, *wq, *wk, *wv, *wo, *att, *pkf, *pvf;
    cudaGetSymbolAddress((void**)&hid, g_hid);
    cudaGetSymbolAddress((void**)&wq, g_wq);   cudaGetSymbolAddress((void**)&wk, g_wk);
    cudaGetSymbolAddress((void**)&wv, g_wv);   cudaGetSymbolAddress((void**)&wo, g_wo);
    cudaGetSymbolAddress((void**)&att, g_att);
    cudaGetSymbolAddress((void**)&pkf, g_kf);  cudaGetSymbolAddress((void**)&pvf, g_vf);

    const int n_big   = 4096 * 4096 / 4;
    const int n_small = 1024 * 4096 / 4;
    conv_f16<<<(n_big + 255) / 256, 256>>>(hidden, hid, n_big);
    conv_f16<<<(n_big + 255) / 256, 256>>>(Wq, wq, n_big);
    conv_f16<<<(n_small + 255) / 256, 256>>>(Wk, wk, n_small);
    conv_f16<<<(n_small + 255) / 256, 256>>>(Wv, wv, n_small);
    conv_f16<<<(n_big + 255) / 256, 256>>>(Wo, wo, n_big);

    cudaFuncSetAttribute(gemm_f16, cudaFuncAttributeMaxDynamicSharedMemorySize, SM_GEMM);
    gemm_f16<<<dim3(32, 32), 256, SM_GEMM>>>(hid, wq, pQ, 4096);
    gemm_f16<<<dim3(8, 32),  256, SM_GEMM>>>(hid, wk, pK, 1024);
    gemm_f16<<<dim3(8, 32),  256, SM_GEMM>>>(hid, wv, pV, 1024);

    {
        int tot = MROWS * HKV_N * 64;
        kv_prep<<<(tot + 255) / 256, 256>>>(pK, pV, cosb, sinb, pkf, pvf);
    }

    cudaFuncSetAttribute(attn_tc, cudaFuncAttributeMaxDynamicSharedMemorySize, SM_ATTN);
    attn_tc<<<dim3(B_N * HQ_N, S_LEN / 64), 256, SM_ATTN>>>(
        pQ, pkf, pvf, cosb, sinb, att);

    gemm_f16<<<dim3(32, 32), 256, SM_GEMM>>>(att, wo, out, 4096);
}